// round 3
// baseline (speedup 1.0000x reference)
#include <cuda_runtime.h>

typedef unsigned long long ULL;

__device__ __forceinline__ ULL pk2(float lo, float hi){
  ULL r; asm("mov.b64 %0, {%1,%2};" : "=l"(r) : "f"(lo), "f"(hi)); return r;
}
__device__ __forceinline__ float2 upk(ULL v){
  float2 r; asm("mov.b64 {%0,%1}, %2;" : "=f"(r.x), "=f"(r.y) : "l"(v)); return r;
}
#define FMA2(d,a,bb,c) asm("fma.rn.f32x2 %0, %1, %2, %3;" : "=l"(d) : "l"(a), "l"(bb), "l"(c))
#define MUL2(d,a,bb)   asm("mul.rn.f32x2 %0, %1, %2;"     : "=l"(d) : "l"(a), "l"(bb))

constexpr int NX_ = 128, NY_ = 128, NT_ = 64;
constexpr float EPS_ = 1e-5f;

// shared memory layout (floats)
constexpr int OFF_H   = 0;                 // h[64][128]
constexpr int OFF_QKV = 64*128;            // qkv[192][128]
constexpr int OFF_ATT = OFF_QKV + 192*128; // att[128][130] / ff-hidden[128][128] / scratch
constexpr int SMEM_FLOATS = OFF_ATT + 128*130;   // 49408 floats = 197632 bytes

// C[o][s] = act( sum_k A[k][s] * W[o*K+k] + Bv[o] ), token dim vectorized by f32x2
template<int OUT, int K, bool RELU>
__device__ __forceinline__ void gemm_tok(const float* __restrict__ A,
                                         const float* __restrict__ W,
                                         const float* __restrict__ Bv,
                                         float* __restrict__ C, int tid)
{
  constexpr int TO = OUT/16;
  const int tx = tid & 15;      // token tile: tokens 8*tx .. 8*tx+7
  const int ty = tid >> 4;      // outputs ty*TO + j
  const int tok = 8*tx;
  ULL acc[TO][4];
#pragma unroll
  for (int j=0;j<TO;j++){
    float b = __ldg(Bv + ty*TO + j);
    ULL bb = pk2(b,b);
#pragma unroll
    for (int p=0;p<4;p++) acc[j][p] = bb;
  }
#pragma unroll 2
  for (int k=0;k<K;k+=2){
    ULL a0[4], a1[4];
#pragma unroll
    for (int p=0;p<4;p++){
      a0[p] = *reinterpret_cast<const ULL*>(A + k*128     + tok + 2*p);
      a1[p] = *reinterpret_cast<const ULL*>(A + (k+1)*128 + tok + 2*p);
    }
#pragma unroll
    for (int j=0;j<TO;j++){
      float2 w2 = __ldg(reinterpret_cast<const float2*>(W + (ty*TO+j)*K + k));
      ULL w0 = pk2(w2.x, w2.x);
      ULL w1 = pk2(w2.y, w2.y);
#pragma unroll
      for (int p=0;p<4;p++){
        FMA2(acc[j][p], a0[p], w0, acc[j][p]);
        FMA2(acc[j][p], a1[p], w1, acc[j][p]);
      }
    }
  }
#pragma unroll
  for (int j=0;j<TO;j++){
#pragma unroll
    for (int p=0;p<4;p++){
      float2 v = upk(acc[j][p]);
      if (RELU){ v.x = fmaxf(v.x,0.f); v.y = fmaxf(v.y,0.f); }
      *reinterpret_cast<float2*>(C + (ty*TO+j)*128 + tok + 2*p) = v;
    }
  }
}

// h[d][s] = LN_d( h[d][s] + r[d][s] ) * gs[d] + gb[d]
__device__ __forceinline__ void add_ln(float* __restrict__ h,
                                       const float* __restrict__ r,
                                       const float* __restrict__ gs,
                                       const float* __restrict__ gb, int tid)
{
  if (tid < 128){
    const int s = tid;
    float sum=0.f, sq=0.f;
#pragma unroll 8
    for (int d=0; d<64; d++){
      float x = h[d*128+s] + r[d*128+s];
      sum += x; sq += x*x;
    }
    float m = sum * (1.f/64.f);
    float var = sq * (1.f/64.f) - m*m;
    float inv = rsqrtf(var + EPS_);
#pragma unroll 8
    for (int d=0; d<64; d++){
      float x = h[d*128+s] + r[d*128+s];
      h[d*128+s] = (x - m)*inv*__ldg(gs+d) + __ldg(gb+d);
    }
  }
}

__device__ __forceinline__ float dper(float diff, float L){
  float m = fmodf(diff + 0.5f*L, L);
  if (m < 0.f) m += L;
  return m - 0.5f*L;
}

__global__ void __launch_bounds__(256, 1)
ff_kernel(const int* __restrict__ q_lin_idx, const int* __restrict__ offs,
          const float* __restrict__ coords, const float* __restrict__ vals,
          const float* __restrict__ lg,
          const float* __restrict__ pw, const float* __restrict__ pb,
          const float* __restrict__ qw, const float* __restrict__ qbias,
          const float* __restrict__ ow, const float* __restrict__ obias,
          const float* __restrict__ l1s, const float* __restrict__ l1b,
          const float* __restrict__ f1w, const float* __restrict__ f1b,
          const float* __restrict__ f2w, const float* __restrict__ f2b,
          const float* __restrict__ l2s, const float* __restrict__ l2b,
          const float* __restrict__ hls, const float* __restrict__ hlb,
          const float* __restrict__ h1w, const float* __restrict__ h1b,
          const float* __restrict__ h2w, const float* __restrict__ h2b,
          float* __restrict__ out)
{
  extern __shared__ float sm[];
  float* h    = sm + OFF_H;     // [64][128]
  float* qkv  = sm + OFF_QKV;   // [192][128]: q 0..63, k 64..127, v 128..191
  float* att  = sm + OFF_ATT;   // [sk][sq] stride 130; also ff hidden / out-proj tmp / scratch

  const int tid = threadIdx.x;
  const int b   = blockIdx.x;

  // ---------------- Phase A: gather + input projection ----------------
  {
    const int s = tid & 127, half = tid >> 7;
    int qi = __ldg(q_lin_idx + b);
    int i  = qi >> 13;            // / (NY*NT) = /8192
    int rr = qi & 8191;
    int j  = rr >> 6;             // / NT
    int kk = rr & 63;
    int di = __ldg(offs + 3*s), dj = __ldg(offs + 3*s + 1), dk = __ldg(offs + 3*s + 2);
    int I = (i + di) & (NX_-1);
    int J = (j + dj) & (NY_-1);
    int T = min(max(kk + dk, 0), NT_-1);
    int nb = (I << 13) + (J << 6) + T;
    float qx = __ldg(coords + 3*qi), qy = __ldg(coords + 3*qi + 1), qt = __ldg(coords + 3*qi + 2);
    float nx = __ldg(coords + 3*nb), ny = __ldg(coords + 3*nb + 1), nt = __ldg(coords + 3*nb + 2);
    float g0 = expf(__ldg(lg+0)), g1 = expf(__ldg(lg+1)), g2 = expf(__ldg(lg+2));
    float f0 = dper(nx - qx, 2.0f) * g0;
    float f1 = dper(ny - qy, 2.0f) * g1;
    float f2 = (nt - qt) * g2;
    float f3 = __ldg(vals + 3*nb), f4 = __ldg(vals + 3*nb + 1), f5 = __ldg(vals + 3*nb + 2);
    for (int d = half*32; d < half*32 + 32; d++){
      float a = __ldg(pb + d);
      a += __ldg(pw + 6*d + 0)*f0 + __ldg(pw + 6*d + 1)*f1 + __ldg(pw + 6*d + 2)*f2
         + __ldg(pw + 6*d + 3)*f3 + __ldg(pw + 6*d + 4)*f4 + __ldg(pw + 6*d + 5)*f5;
      h[d*128 + s] = a;
    }
  }
  __syncthreads();

  // ---------------- Phase B: 2 transformer layers ----------------
  for (int l = 0; l < 2; l++){
    // qkv projection
    gemm_tok<192,64,false>(h, qw + l*192*64, qbias + l*192, qkv, tid);
    __syncthreads();

    // attention, head by head
    for (int hd = 0; hd < 4; hd++){
      // scores: att[sk][sq] = 0.25 * sum_di q[di][sq]*k[di][sk]
      {
        const float* qb2 = qkv + (hd*16)*128;
        const float* kb  = qkv + (64 + hd*16)*128;
        const int tx = tid & 15, ty = tid >> 4;  // tx: sk tile of 8, ty: sq tile of 8
        ULL acc[8][4];
        ULL z = pk2(0.f, 0.f);
#pragma unroll
        for (int jj=0;jj<8;jj++)
#pragma unroll
          for (int p=0;p<4;p++) acc[jj][p] = z;
#pragma unroll 2
        for (int di=0; di<16; di++){
          ULL qp[4];
#pragma unroll
          for (int p=0;p<4;p++)
            qp[p] = *reinterpret_cast<const ULL*>(qb2 + di*128 + 8*ty + 2*p);
          float kv[8];
#pragma unroll
          for (int jj=0;jj<8;jj+=2){
            float2 k2 = *reinterpret_cast<const float2*>(kb + di*128 + 8*tx + jj);
            kv[jj] = k2.x; kv[jj+1] = k2.y;
          }
#pragma unroll
          for (int jj=0;jj<8;jj++){
            ULL kd = pk2(kv[jj], kv[jj]);
#pragma unroll
            for (int p=0;p<4;p++) FMA2(acc[jj][p], qp[p], kd, acc[jj][p]);
          }
        }
        ULL sc = pk2(0.25f, 0.25f);
#pragma unroll
        for (int jj=0;jj<8;jj++)
#pragma unroll
          for (int p=0;p<4;p++){
            ULL v; MUL2(v, acc[jj][p], sc);
            *reinterpret_cast<ULL*>(att + (8*tx+jj)*130 + 8*ty + 2*p) = v;
          }
      }
      __syncthreads();

      // softmax over sk for each sq row (warp per row)
      {
        const int w = tid >> 5, ln = tid & 31;
        for (int m = 0; m < 16; m++){
          int r = 8*m + w;
          float v[4];
#pragma unroll
          for (int u=0;u<4;u++) v[u] = att[(ln + 32*u)*130 + r];
          float mx = fmaxf(fmaxf(v[0],v[1]), fmaxf(v[2],v[3]));
#pragma unroll
          for (int off=16; off; off>>=1) mx = fmaxf(mx, __shfl_xor_sync(0xffffffffu, mx, off));
          float e[4]; float smv = 0.f;
#pragma unroll
          for (int u=0;u<4;u++){ e[u] = __expf(v[u]-mx); smv += e[u]; }
#pragma unroll
          for (int off=16; off; off>>=1) smv += __shfl_xor_sync(0xffffffffu, smv, off);
          float inv = 1.0f / smv;
#pragma unroll
          for (int u=0;u<4;u++) att[(ln + 32*u)*130 + r] = e[u]*inv;
        }
      }
      __syncthreads();

      // o[dv][sq] = sum_sk att[sk][sq] * v[dv][sk]  (write over q slice of this head)
      if (tid < 128){
        const int pg = tid & 15, dg = tid >> 4;  // pg: sq tile of 8, dg: dv pair
        float* obp      = qkv + (hd*16 + 2*dg)*128;
        const float* vb = qkv + (128 + hd*16 + 2*dg)*128;
        ULL a0[4], a1[4];
        ULL z = pk2(0.f,0.f);
#pragma unroll
        for (int p=0;p<4;p++){ a0[p]=z; a1[p]=z; }
#pragma unroll 4
        for (int sk=0; sk<128; sk++){
          float v0 = vb[sk], v1 = vb[128+sk];
          ULL vd0 = pk2(v0,v0), vd1 = pk2(v1,v1);
#pragma unroll
          for (int p=0;p<4;p++){
            ULL ap = *reinterpret_cast<const ULL*>(att + sk*130 + 8*pg + 2*p);
            FMA2(a0[p], ap, vd0, a0[p]);
            FMA2(a1[p], ap, vd1, a1[p]);
          }
        }
#pragma unroll
        for (int p=0;p<4;p++){
          *reinterpret_cast<ULL*>(obp + 8*pg + 2*p)       = a0[p];
          *reinterpret_cast<ULL*>(obp + 128 + 8*pg + 2*p) = a1[p];
        }
      }
      __syncthreads();
    }

    // output projection (reads o from q region), tmp into att region
    gemm_tok<64,64,false>(qkv, ow + l*64*64, obias + l*64, att, tid);
    __syncthreads();
    add_ln(h, att, l1s + l*64, l1b + l*64, tid);
    __syncthreads();

    // FF: hidden = relu(h @ ff1^T + b1) in att region; then ff2 into qkv region
    gemm_tok<128,64,true>(h, f1w + l*128*64, f1b + l*128, att, tid);
    __syncthreads();
    gemm_tok<64,128,false>(att, f2w + l*64*128, f2b + l*64, qkv, tid);
    __syncthreads();
    add_ln(h, qkv, l2s + l*64, l2b + l*64, tid);
    __syncthreads();
  }

  // ---------------- Phase C: mean pool + head MLP ----------------
  float* scr = att;
  {
    const int d = tid & 63, qt = tid >> 6;   // 4 quarters of 32 tokens
    float s0 = 0.f;
    for (int s2 = qt*32; s2 < qt*32 + 32; s2++) s0 += h[d*128 + s2];
    scr[qt*64 + d] = s0;
  }
  __syncthreads();
  if (tid < 64){
    float hm = (scr[tid] + scr[64+tid] + scr[128+tid] + scr[192+tid]) * (1.0f/128.0f);
    scr[256 + tid] = hm;
  }
  __syncthreads();
  if (tid < 32){
    float a = scr[256 + tid], c = scr[256 + 32 + tid];
    float sum = a + c, sq = a*a + c*c;
#pragma unroll
    for (int off=16; off; off>>=1){
      sum += __shfl_xor_sync(0xffffffffu, sum, off);
      sq  += __shfl_xor_sync(0xffffffffu, sq,  off);
    }
    if (tid == 0){
      float m = sum * (1.f/64.f);
      scr[320] = m;
      scr[321] = rsqrtf(sq * (1.f/64.f) - m*m + EPS_);
    }
  }
  __syncthreads();
  if (tid < 64){
    float m = scr[320], inv = scr[321];
    scr[384 + tid] = (scr[256+tid] - m)*inv*__ldg(hls+tid) + __ldg(hlb+tid);
  }
  __syncthreads();
  if (tid < 64){
    float acc = __ldg(h1b + tid);
    for (int k=0;k<64;k++) acc += scr[384+k]*__ldg(h1w + tid*64 + k);
    scr[448 + tid] = 0.5f*acc*(1.0f + erff(acc*0.70710678118654752f));
  }
  __syncthreads();
  if (tid < 3){
    float acc = __ldg(h2b + tid);
    for (int k=0;k<64;k++) acc += scr[448+k]*__ldg(h2w + tid*64 + k);
    out[b*3 + tid] = acc;
  }
}

extern "C" void kernel_launch(void* const* d_in, const int* in_sizes, int n_in,
                              void* d_out, int out_size)
{
  const int*   qli    = (const int*)  d_in[0];
  const int*   offs   = (const int*)  d_in[1];
  const float* coords = (const float*)d_in[2];
  const float* vals   = (const float*)d_in[3];
  const float* lg     = (const float*)d_in[4];
  const float* pw     = (const float*)d_in[5];
  const float* pb     = (const float*)d_in[6];
  const float* qw     = (const float*)d_in[7];
  const float* qb     = (const float*)d_in[8];
  const float* ow     = (const float*)d_in[9];
  const float* ob     = (const float*)d_in[10];
  const float* l1s    = (const float*)d_in[11];
  const float* l1b    = (const float*)d_in[12];
  const float* f1w    = (const float*)d_in[13];
  const float* f1b    = (const float*)d_in[14];
  const float* f2w    = (const float*)d_in[15];
  const float* f2b    = (const float*)d_in[16];
  const float* l2s    = (const float*)d_in[17];
  const float* l2b    = (const float*)d_in[18];
  const float* hls    = (const float*)d_in[19];
  const float* hlb    = (const float*)d_in[20];
  const float* h1w    = (const float*)d_in[21];
  const float* h1b    = (const float*)d_in[22];
  const float* h2w    = (const float*)d_in[23];
  const float* h2b    = (const float*)d_in[24];
  float* out = (float*)d_out;
  const int B = in_sizes[0];

  cudaFuncSetAttribute(ff_kernel, cudaFuncAttributeMaxDynamicSharedMemorySize,
                       SMEM_FLOATS * (int)sizeof(float));
  ff_kernel<<<B, 256, SMEM_FLOATS * sizeof(float)>>>(
      qli, offs, coords, vals, lg, pw, pb, qw, qb, ow, ob,
      l1s, l1b, f1w, f1b, f2w, f2b, l2s, l2b,
      hls, hlb, h1w, h1b, h2w, h2b, out);
}

// round 4
// speedup vs baseline: 1.1729x; 1.1729x over previous
#include <cuda_runtime.h>

typedef unsigned long long ULL;

__device__ __forceinline__ ULL pk2(float lo, float hi){
  ULL r; asm("mov.b64 %0, {%1,%2};" : "=l"(r) : "f"(lo), "f"(hi)); return r;
}
__device__ __forceinline__ float2 upk(ULL v){
  float2 r; asm("mov.b64 {%0,%1}, %2;" : "=f"(r.x), "=f"(r.y) : "l"(v)); return r;
}
#define FMA2(d,a,bb,c) asm("fma.rn.f32x2 %0, %1, %2, %3;" : "=l"(d) : "l"(a), "l"(bb), "l"(c))
#define MUL2(d,a,bb)   asm("mul.rn.f32x2 %0, %1, %2;"     : "=l"(d) : "l"(a), "l"(bb))

constexpr int NX_ = 128, NY_ = 128, NT_ = 64;
constexpr float EPS_ = 1e-5f;

// shared layout (floats)
constexpr int OFF_H   = 0;         // h[64][128]
constexpr int OFF_QKV = 8192;      // qkv[192][128]: q 0..63, k 64..127, v 128..191
constexpr int OFF_ATT = 32768;     // att[128][128] (also ff hidden / out-proj tmp)
constexpr int OFF_AUX = 49152;     // 3*2048 AV partials; also LN scratch / phase-C scratch
constexpr int OFF_RS  = 55296;     // 512 rowsum partials + 128 inv
constexpr int SMEM_FLOATS = 55936; // 223,744 bytes

// C[o][s] = act( sum_k A[k][s]*W[o*K+k] + Bv[o] ), 512 threads
template<int OUT, int K, bool RELU>
__device__ __forceinline__ void gemm_tok(const float* __restrict__ A,
                                         const float* __restrict__ W,
                                         const float* __restrict__ Bv,
                                         float* __restrict__ C, int tid)
{
  constexpr int TO = OUT/32;
  const int tx = tid & 15;   // tokens 8*tx..8*tx+7
  const int g  = tid >> 4;   // 0..31, outputs g*TO+j
  const int tok = 8*tx;
  ULL acc[TO][4];
#pragma unroll
  for (int j=0;j<TO;j++){
    float b = __ldg(Bv + g*TO + j);
    ULL bb = pk2(b,b);
#pragma unroll
    for (int p=0;p<4;p++) acc[j][p] = bb;
  }
#pragma unroll 2
  for (int k=0;k<K;k+=2){
    ULL a0[4], a1[4];
#pragma unroll
    for (int p=0;p<4;p++){
      a0[p] = *reinterpret_cast<const ULL*>(A + k*128     + tok + 2*p);
      a1[p] = *reinterpret_cast<const ULL*>(A + (k+1)*128 + tok + 2*p);
    }
#pragma unroll
    for (int j=0;j<TO;j++){
      float2 w2 = __ldg(reinterpret_cast<const float2*>(W + (g*TO+j)*K + k));
      ULL w0 = pk2(w2.x, w2.x);
      ULL w1 = pk2(w2.y, w2.y);
#pragma unroll
      for (int p=0;p<4;p++){
        FMA2(acc[j][p], a0[p], w0, acc[j][p]);
        FMA2(acc[j][p], a1[p], w1, acc[j][p]);
      }
    }
  }
#pragma unroll
  for (int j=0;j<TO;j++){
#pragma unroll
    for (int p=0;p<4;p++){
      float2 v = upk(acc[j][p]);
      if (RELU){ v.x = fmaxf(v.x,0.f); v.y = fmaxf(v.y,0.f); }
      *reinterpret_cast<float2*>(C + (g*TO+j)*128 + tok + 2*p) = v;
    }
  }
}

// h = LN(h + r); parallel over 512 threads, uses aux scratch; contains 2 syncs
__device__ __forceinline__ void add_ln(float* __restrict__ h,
                                       const float* __restrict__ r,
                                       const float* __restrict__ gs,
                                       const float* __restrict__ gb,
                                       float* __restrict__ aux, int tid)
{
  const int s = tid & 127, g = tid >> 7;
  float sum=0.f, sq=0.f;
#pragma unroll
  for (int d=16*g; d<16*g+16; d++){
    float x = h[d*128+s] + r[d*128+s];
    h[d*128+s] = x;
    sum += x; sq += x*x;
  }
  aux[g*128+s] = sum;
  aux[512 + g*128+s] = sq;
  __syncthreads();
  if (tid < 128){
    float S = aux[tid] + aux[128+tid] + aux[256+tid] + aux[384+tid];
    float Q = aux[512+tid] + aux[640+tid] + aux[768+tid] + aux[896+tid];
    float m = S * (1.f/64.f);
    float inv = rsqrtf(Q * (1.f/64.f) - m*m + EPS_);
    aux[1024+tid] = m;
    aux[1152+tid] = inv;
  }
  __syncthreads();
  {
    float m = aux[1024+s], inv = aux[1152+s];
#pragma unroll
    for (int d=16*g; d<16*g+16; d++){
      h[d*128+s] = (h[d*128+s] - m)*inv*__ldg(gs+d) + __ldg(gb+d);
    }
  }
}

__device__ __forceinline__ float dper(float diff, float L){
  float m = fmodf(diff + 0.5f*L, L);
  if (m < 0.f) m += L;
  return m - 0.5f*L;
}

__global__ void __launch_bounds__(512, 1)
ff_kernel(const int* __restrict__ q_lin_idx, const int* __restrict__ offs,
          const float* __restrict__ coords, const float* __restrict__ vals,
          const float* __restrict__ lg,
          const float* __restrict__ pw, const float* __restrict__ pb,
          const float* __restrict__ qw, const float* __restrict__ qbias,
          const float* __restrict__ ow, const float* __restrict__ obias,
          const float* __restrict__ l1s, const float* __restrict__ l1b,
          const float* __restrict__ f1w, const float* __restrict__ f1b,
          const float* __restrict__ f2w, const float* __restrict__ f2b,
          const float* __restrict__ l2s, const float* __restrict__ l2b,
          const float* __restrict__ hls, const float* __restrict__ hlb,
          const float* __restrict__ h1w, const float* __restrict__ h1b,
          const float* __restrict__ h2w, const float* __restrict__ h2b,
          float* __restrict__ out)
{
  extern __shared__ float sm[];
  float* h    = sm + OFF_H;
  float* qkv  = sm + OFF_QKV;
  float* att  = sm + OFF_ATT;
  float* aux  = sm + OFF_AUX;
  float* rs   = sm + OFF_RS;        // 512 partials
  float* rsinv= sm + OFF_RS + 512;  // 128 inverses

  const int tid = threadIdx.x;
  const int b   = blockIdx.x;

  // ---------------- Phase A: gather + input projection ----------------
  {
    const int s = tid & 127, g = tid >> 7;
    int qi = __ldg(q_lin_idx + b);
    int i  = qi >> 13;
    int rr = qi & 8191;
    int j  = rr >> 6;
    int kk = rr & 63;
    int di = __ldg(offs + 3*s), dj = __ldg(offs + 3*s + 1), dk = __ldg(offs + 3*s + 2);
    int I = (i + di) & (NX_-1);
    int J = (j + dj) & (NY_-1);
    int T = min(max(kk + dk, 0), NT_-1);
    int nb = (I << 13) + (J << 6) + T;
    float qx = __ldg(coords + 3*qi), qy = __ldg(coords + 3*qi + 1), qt = __ldg(coords + 3*qi + 2);
    float nx = __ldg(coords + 3*nb), ny = __ldg(coords + 3*nb + 1), nt = __ldg(coords + 3*nb + 2);
    float g0 = expf(__ldg(lg+0)), g1 = expf(__ldg(lg+1)), g2 = expf(__ldg(lg+2));
    float f0 = dper(nx - qx, 2.0f) * g0;
    float f1 = dper(ny - qy, 2.0f) * g1;
    float f2 = (nt - qt) * g2;
    float f3 = __ldg(vals + 3*nb), f4 = __ldg(vals + 3*nb + 1), f5 = __ldg(vals + 3*nb + 2);
#pragma unroll
    for (int d = g*16; d < g*16 + 16; d++){
      float a = __ldg(pb + d);
      a += __ldg(pw + 6*d + 0)*f0 + __ldg(pw + 6*d + 1)*f1 + __ldg(pw + 6*d + 2)*f2
         + __ldg(pw + 6*d + 3)*f3 + __ldg(pw + 6*d + 4)*f4 + __ldg(pw + 6*d + 5)*f5;
      h[d*128 + s] = a;
    }
  }
  __syncthreads();

  // ---------------- Phase B: 2 transformer layers ----------------
  for (int l = 0; l < 2; l++){
    gemm_tok<192,64,false>(h, qw + l*192*64, qbias + l*192, qkv, tid);
    __syncthreads();

    for (int hd = 0; hd < 4; hd++){
      // ---- QK^T with fused exp: att[sk][sq] = exp(0.25*q.k) ----
      {
        const float* qb2 = qkv + (hd*16)*128;
        const float* kb  = qkv + (64 + hd*16)*128;
        const int tx = tid & 31;   // sk tile of 4
        const int ty = tid >> 5;   // sq tile of 8 (warp-uniform)
        ULL acc[4][4];
        ULL z = pk2(0.f, 0.f);
#pragma unroll
        for (int jj=0;jj<4;jj++)
#pragma unroll
          for (int p=0;p<4;p++) acc[jj][p] = z;
#pragma unroll 4
        for (int di=0; di<16; di++){
          ULL qp[4];
#pragma unroll
          for (int p=0;p<4;p++)
            qp[p] = *reinterpret_cast<const ULL*>(qb2 + di*128 + 8*ty + 2*p);
          float4 kf = *reinterpret_cast<const float4*>(kb + di*128 + 4*tx);
          float kvv[4] = {kf.x, kf.y, kf.z, kf.w};
#pragma unroll
          for (int jj=0;jj<4;jj++){
            ULL kd = pk2(kvv[jj], kvv[jj]);
#pragma unroll
            for (int p=0;p<4;p++) FMA2(acc[jj][p], qp[p], kd, acc[jj][p]);
          }
        }
#pragma unroll
        for (int jj=0;jj<4;jj++)
#pragma unroll
          for (int p=0;p<4;p++){
            float2 v = upk(acc[jj][p]);
            v.x = __expf(0.25f * v.x);
            v.y = __expf(0.25f * v.y);
            *reinterpret_cast<ULL*>(att + (4*tx+jj)*128 + 8*ty + 2*p) = pk2(v.x, v.y);
          }
      }
      __syncthreads();

      // ---- row-sum over sk (contiguous reads), then inverse ----
      {
        const int sq = tid & 127, rg = tid >> 7;
        float smv = 0.f;
#pragma unroll 8
        for (int i2=0; i2<32; i2++) smv += att[(rg*32 + i2)*128 + sq];
        rs[rg*128 + sq] = smv;
      }
      __syncthreads();
      if (tid < 128)
        rsinv[tid] = 1.0f / (rs[tid] + rs[128+tid] + rs[256+tid] + rs[384+tid]);
      __syncthreads();

      // ---- AV: o[dv][sq] = inv[sq] * sum_sk att[sk][sq]*v[dv][sk] ----
      {
        const int pg = tid & 31;        // sq tile of 4
        const int dq = (tid>>5) & 3;    // dv quad: rows 4*dq..4*dq+3 of head
        const int hf = tid >> 7;        // sk quarter
        const float* vb = qkv + (128 + hd*16 + 4*dq)*128;
        ULL a0r[4], a1r[4];
        ULL z = pk2(0.f,0.f);
#pragma unroll
        for (int r2=0;r2<4;r2++){ a0r[r2]=z; a1r[r2]=z; }
        for (int sk0 = hf*32; sk0 < hf*32 + 32; sk0 += 4){
          float4 v0 = *reinterpret_cast<const float4*>(vb + sk0);
          float4 v1 = *reinterpret_cast<const float4*>(vb + 128 + sk0);
          float4 v2 = *reinterpret_cast<const float4*>(vb + 256 + sk0);
          float4 v3 = *reinterpret_cast<const float4*>(vb + 384 + sk0);
          float vv[4][4] = {{v0.x,v0.y,v0.z,v0.w},{v1.x,v1.y,v1.z,v1.w},
                            {v2.x,v2.y,v2.z,v2.w},{v3.x,v3.y,v3.z,v3.w}};
#pragma unroll
          for (int s4=0; s4<4; s4++){
            float4 av = *reinterpret_cast<const float4*>(att + (sk0+s4)*128 + 4*pg);
            ULL a0 = pk2(av.x, av.y), a1 = pk2(av.z, av.w);
#pragma unroll
            for (int r2=0;r2<4;r2++){
              ULL vd = pk2(vv[r2][s4], vv[r2][s4]);
              FMA2(a0r[r2], a0, vd, a0r[r2]);
              FMA2(a1r[r2], a1, vd, a1r[r2]);
            }
          }
        }
        ULL i0 = *reinterpret_cast<const ULL*>(rsinv + 4*pg);
        ULL i1 = *reinterpret_cast<const ULL*>(rsinv + 4*pg + 2);
        float* dst = (hf==0) ? (qkv + (hd*16 + 4*dq)*128)
                             : (aux + (hf-1)*2048 + 4*dq*128);
#pragma unroll
        for (int r2=0;r2<4;r2++){
          MUL2(a0r[r2], a0r[r2], i0);
          MUL2(a1r[r2], a1r[r2], i1);
          *reinterpret_cast<ULL*>(dst + r2*128 + 4*pg)     = a0r[r2];
          *reinterpret_cast<ULL*>(dst + r2*128 + 4*pg + 2) = a1r[r2];
        }
      }
      __syncthreads();

      // ---- combine sk-quarter partials into o ----
      {
        float4* ob = reinterpret_cast<float4*>(qkv + hd*16*128);
        const float4* p1 = reinterpret_cast<const float4*>(aux);
        const float4* p2 = reinterpret_cast<const float4*>(aux + 2048);
        const float4* p3 = reinterpret_cast<const float4*>(aux + 4096);
        float4 o = ob[tid], q1 = p1[tid], q2 = p2[tid], q3 = p3[tid];
        o.x += q1.x + q2.x + q3.x;
        o.y += q1.y + q2.y + q3.y;
        o.z += q1.z + q2.z + q3.z;
        o.w += q1.w + q2.w + q3.w;
        ob[tid] = o;
      }
      __syncthreads();
    }

    gemm_tok<64,64,false>(qkv, ow + l*64*64, obias + l*64, att, tid);
    __syncthreads();
    add_ln(h, att, l1s + l*64, l1b + l*64, aux, tid);
    __syncthreads();

    gemm_tok<128,64,true>(h, f1w + l*128*64, f1b + l*128, att, tid);
    __syncthreads();
    gemm_tok<64,128,false>(att, f2w + l*64*128, f2b + l*64, qkv, tid);
    __syncthreads();
    add_ln(h, qkv, l2s + l*64, l2b + l*64, aux, tid);
    __syncthreads();
  }

  // ---------------- Phase C: mean pool + head MLP ----------------
  {
    const int d = tid & 63, oc = tid >> 6;  // 8 groups of 16 tokens
    float s0 = 0.f;
#pragma unroll
    for (int t = oc*16; t < oc*16 + 16; t++) s0 += h[d*128 + t];
    aux[oc*64 + d] = s0;
  }
  __syncthreads();
  if (tid < 64){
    float hm = 0.f;
#pragma unroll
    for (int o2=0;o2<8;o2++) hm += aux[o2*64 + tid];
    aux[512 + tid] = hm * (1.0f/128.0f);
  }
  __syncthreads();
  if (tid < 32){
    float a = aux[512 + tid], c = aux[512 + 32 + tid];
    float sum = a + c, sq = a*a + c*c;
#pragma unroll
    for (int off=16; off; off>>=1){
      sum += __shfl_xor_sync(0xffffffffu, sum, off);
      sq  += __shfl_xor_sync(0xffffffffu, sq,  off);
    }
    if (tid == 0){
      float m = sum * (1.f/64.f);
      aux[576] = m;
      aux[577] = rsqrtf(sq * (1.f/64.f) - m*m + EPS_);
    }
  }
  __syncthreads();
  if (tid < 64){
    float m = aux[576], inv = aux[577];
    aux[640 + tid] = (aux[512+tid] - m)*inv*__ldg(hls+tid) + __ldg(hlb+tid);
  }
  __syncthreads();
  if (tid < 64){
    float acc = __ldg(h1b + tid);
#pragma unroll 8
    for (int k=0;k<64;k++) acc += aux[640+k]*__ldg(h1w + tid*64 + k);
    aux[704 + tid] = 0.5f*acc*(1.0f + erff(acc*0.70710678118654752f));
  }
  __syncthreads();
  if (tid < 3){
    float acc = __ldg(h2b + tid);
#pragma unroll 8
    for (int k=0;k<64;k++) acc += aux[704+k]*__ldg(h2w + tid*64 + k);
    out[b*3 + tid] = acc;
  }
}

extern "C" void kernel_launch(void* const* d_in, const int* in_sizes, int n_in,
                              void* d_out, int out_size)
{
  const int*   qli    = (const int*)  d_in[0];
  const int*   offs   = (const int*)  d_in[1];
  const float* coords = (const float*)d_in[2];
  const float* vals   = (const float*)d_in[3];
  const float* lg     = (const float*)d_in[4];
  const float* pw     = (const float*)d_in[5];
  const float* pb     = (const float*)d_in[6];
  const float* qw     = (const float*)d_in[7];
  const float* qb     = (const float*)d_in[8];
  const float* ow     = (const float*)d_in[9];
  const float* ob     = (const float*)d_in[10];
  const float* l1s    = (const float*)d_in[11];
  const float* l1b    = (const float*)d_in[12];
  const float* f1w    = (const float*)d_in[13];
  const float* f1b    = (const float*)d_in[14];
  const float* f2w    = (const float*)d_in[15];
  const float* f2b    = (const float*)d_in[16];
  const float* l2s    = (const float*)d_in[17];
  const float* l2b    = (const float*)d_in[18];
  const float* hls    = (const float*)d_in[19];
  const float* hlb    = (const float*)d_in[20];
  const float* h1w    = (const float*)d_in[21];
  const float* h1b    = (const float*)d_in[22];
  const float* h2w    = (const float*)d_in[23];
  const float* h2b    = (const float*)d_in[24];
  float* out = (float*)d_out;
  const int B = in_sizes[0];

  cudaFuncSetAttribute(ff_kernel, cudaFuncAttributeMaxDynamicSharedMemorySize,
                       SMEM_FLOATS * (int)sizeof(float));
  ff_kernel<<<B, 512, SMEM_FLOATS * sizeof(float)>>>(
      qli, offs, coords, vals, lg, pw, pb, qw, qb, ow, ob,
      l1s, l1b, f1w, f1b, f2w, f2b, l2s, l2b,
      hls, hlb, h1w, h1b, h2w, h2b, out);
}

// round 5
// speedup vs baseline: 1.3775x; 1.1744x over previous
#include <cuda_runtime.h>

typedef unsigned long long ULL;

__device__ __forceinline__ ULL pk2(float lo, float hi){
  ULL r; asm("mov.b64 %0, {%1,%2};" : "=l"(r) : "f"(lo), "f"(hi)); return r;
}
__device__ __forceinline__ float2 upk(ULL v){
  float2 r; asm("mov.b64 {%0,%1}, %2;" : "=f"(r.x), "=f"(r.y) : "l"(v)); return r;
}
#define FMA2(d,a,bb,c) asm("fma.rn.f32x2 %0, %1, %2, %3;" : "=l"(d) : "l"(a), "l"(bb), "l"(c))
#define MUL2(d,a,bb)   asm("mul.rn.f32x2 %0, %1, %2;"     : "=l"(d) : "l"(a), "l"(bb))

constexpr int NX_ = 128, NY_ = 128, NT_ = 64;
constexpr float EPS_ = 1e-5f;

// shared layout (floats)
constexpr int OFF_H   = 0;         // h[64][128]
constexpr int OFF_QKV = 8192;      // qkv[192][128]: q 0..63, k 64..127, v 128..191
constexpr int OFF_ATT = 32768;     // att[128][128] (also ff hidden / out-proj tmp)
constexpr int OFF_AUX = 49152;     // 3*2048 AV partials; LN scratch / phase-C scratch
constexpr int OFF_RS  = 55296;     // 512 rowsum partials
constexpr int SMEM_FLOATS = 55808; // 223,232 bytes

// C[o][s] = act( sum_k A[k][s]*W[o*K+k] + Bv[o] ), 512 threads.
// TPT tokens per thread; out-group index is warp-uniform -> weight LDGs broadcast.
template<int OUT, int K, bool RELU, int TPT>
__device__ __forceinline__ void gemm_tok(const float* __restrict__ A,
                                         const float* __restrict__ W,
                                         const float* __restrict__ Bv,
                                         float* __restrict__ C, int tid)
{
  constexpr int NTG = 128/TPT;      // token groups (>=32 so g is warp-uniform)
  constexpr int NOG = 512/NTG;      // output groups
  constexpr int TO  = OUT/NOG;      // outputs per thread
  constexpr int PU  = TPT/2;        // ULLs per token tile
  const int tx  = tid & (NTG-1);
  const int g   = tid / NTG;        // warp-uniform
  const int tok = TPT*tx;
  ULL acc[TO][PU];
#pragma unroll
  for (int j=0;j<TO;j++){
    float b = __ldg(Bv + g*TO + j);
    ULL bb = pk2(b,b);
#pragma unroll
    for (int p=0;p<PU;p++) acc[j][p] = bb;
  }
#pragma unroll 4
  for (int k=0;k<K;k+=2){
    ULL a0[PU], a1[PU];
#pragma unroll
    for (int p=0;p<PU;p++){
      a0[p] = *reinterpret_cast<const ULL*>(A + k*128     + tok + 2*p);
      a1[p] = *reinterpret_cast<const ULL*>(A + (k+1)*128 + tok + 2*p);
    }
#pragma unroll
    for (int j=0;j<TO;j++){
      float2 w2 = __ldg(reinterpret_cast<const float2*>(W + (g*TO+j)*K + k));
      ULL w0 = pk2(w2.x, w2.x);
      ULL w1 = pk2(w2.y, w2.y);
#pragma unroll
      for (int p=0;p<PU;p++){
        FMA2(acc[j][p], a0[p], w0, acc[j][p]);
        FMA2(acc[j][p], a1[p], w1, acc[j][p]);
      }
    }
  }
#pragma unroll
  for (int j=0;j<TO;j++){
#pragma unroll
    for (int p=0;p<PU;p++){
      float2 v = upk(acc[j][p]);
      if (RELU){ v.x = fmaxf(v.x,0.f); v.y = fmaxf(v.y,0.f); }
      *reinterpret_cast<float2*>(C + (g*TO+j)*128 + tok + 2*p) = v;
    }
  }
}

// h = LN(h + r); parallel over 512 threads; 2 internal syncs
__device__ __forceinline__ void add_ln(float* __restrict__ h,
                                       const float* __restrict__ r,
                                       const float* __restrict__ gs,
                                       const float* __restrict__ gb,
                                       float* __restrict__ aux, int tid)
{
  const int s = tid & 127, g = tid >> 7;
  float sum=0.f, sq=0.f;
#pragma unroll
  for (int d=16*g; d<16*g+16; d++){
    float x = h[d*128+s] + r[d*128+s];
    h[d*128+s] = x;
    sum += x; sq += x*x;
  }
  aux[g*128+s] = sum;
  aux[512 + g*128+s] = sq;
  __syncthreads();
  if (tid < 128){
    float S = aux[tid] + aux[128+tid] + aux[256+tid] + aux[384+tid];
    float Q = aux[512+tid] + aux[640+tid] + aux[768+tid] + aux[896+tid];
    float m = S * (1.f/64.f);
    float inv = rsqrtf(Q * (1.f/64.f) - m*m + EPS_);
    aux[1024+tid] = m;
    aux[1152+tid] = inv;
  }
  __syncthreads();
  {
    float m = aux[1024+s], inv = aux[1152+s];
#pragma unroll
    for (int d=16*g; d<16*g+16; d++){
      h[d*128+s] = (h[d*128+s] - m)*inv*__ldg(gs+d) + __ldg(gb+d);
    }
  }
}

__device__ __forceinline__ float dper(float diff, float L){
  float m = fmodf(diff + 0.5f*L, L);
  if (m < 0.f) m += L;
  return m - 0.5f*L;
}

__global__ void __launch_bounds__(512, 1)
ff_kernel(const int* __restrict__ q_lin_idx, const int* __restrict__ offs,
          const float* __restrict__ coords, const float* __restrict__ vals,
          const float* __restrict__ lg,
          const float* __restrict__ pw, const float* __restrict__ pb,
          const float* __restrict__ qw, const float* __restrict__ qbias,
          const float* __restrict__ ow, const float* __restrict__ obias,
          const float* __restrict__ l1s, const float* __restrict__ l1b,
          const float* __restrict__ f1w, const float* __restrict__ f1b,
          const float* __restrict__ f2w, const float* __restrict__ f2b,
          const float* __restrict__ l2s, const float* __restrict__ l2b,
          const float* __restrict__ hls, const float* __restrict__ hlb,
          const float* __restrict__ h1w, const float* __restrict__ h1b,
          const float* __restrict__ h2w, const float* __restrict__ h2b,
          float* __restrict__ out)
{
  extern __shared__ float sm[];
  float* h    = sm + OFF_H;
  float* qkv  = sm + OFF_QKV;
  float* att  = sm + OFF_ATT;
  float* aux  = sm + OFF_AUX;
  float* rs   = sm + OFF_RS;        // 4*128 rowsum partials

  const int tid = threadIdx.x;
  const int b   = blockIdx.x;

  // ---------------- Phase A: gather + input projection ----------------
  {
    const int s = tid & 127, g = tid >> 7;
    int qi = __ldg(q_lin_idx + b);
    int i  = qi >> 13;
    int rr = qi & 8191;
    int j  = rr >> 6;
    int kk = rr & 63;
    int di = __ldg(offs + 3*s), dj = __ldg(offs + 3*s + 1), dk = __ldg(offs + 3*s + 2);
    int I = (i + di) & (NX_-1);
    int J = (j + dj) & (NY_-1);
    int T = min(max(kk + dk, 0), NT_-1);
    int nb = (I << 13) + (J << 6) + T;
    float qx = __ldg(coords + 3*qi), qy = __ldg(coords + 3*qi + 1), qt = __ldg(coords + 3*qi + 2);
    float nx = __ldg(coords + 3*nb), ny = __ldg(coords + 3*nb + 1), nt = __ldg(coords + 3*nb + 2);
    float g0 = expf(__ldg(lg+0)), g1 = expf(__ldg(lg+1)), g2 = expf(__ldg(lg+2));
    float f0 = dper(nx - qx, 2.0f) * g0;
    float f1 = dper(ny - qy, 2.0f) * g1;
    float f2 = (nt - qt) * g2;
    float f3 = __ldg(vals + 3*nb), f4 = __ldg(vals + 3*nb + 1), f5 = __ldg(vals + 3*nb + 2);
#pragma unroll
    for (int d = g*16; d < g*16 + 16; d++){
      float a = __ldg(pb + d);
      a += __ldg(pw + 6*d + 0)*f0 + __ldg(pw + 6*d + 1)*f1 + __ldg(pw + 6*d + 2)*f2
         + __ldg(pw + 6*d + 3)*f3 + __ldg(pw + 6*d + 4)*f4 + __ldg(pw + 6*d + 5)*f5;
      h[d*128 + s] = a;
    }
  }
  __syncthreads();

  // ---------------- Phase B: 2 transformer layers ----------------
  for (int l = 0; l < 2; l++){
    gemm_tok<192,64,false,4>(h, qw + l*192*64, qbias + l*192, qkv, tid);
    __syncthreads();

    for (int hd = 0; hd < 4; hd++){
      // ---- QK^T with fused exp: att[sk][sq] = exp(0.25*q.k) ----
      {
        const float* qb2 = qkv + (hd*16)*128;
        const float* kb  = qkv + (64 + hd*16)*128;
        const int tx = tid & 31;   // sk tile of 4
        const int ty = tid >> 5;   // sq tile of 8 (warp-uniform)
        ULL acc[4][4];
        ULL z = pk2(0.f, 0.f);
#pragma unroll
        for (int jj=0;jj<4;jj++)
#pragma unroll
          for (int p=0;p<4;p++) acc[jj][p] = z;
#pragma unroll 4
        for (int di=0; di<16; di++){
          ULL qp[4];
#pragma unroll
          for (int p=0;p<4;p++)
            qp[p] = *reinterpret_cast<const ULL*>(qb2 + di*128 + 8*ty + 2*p);
          float4 kf = *reinterpret_cast<const float4*>(kb + di*128 + 4*tx);
          float kvv[4] = {kf.x, kf.y, kf.z, kf.w};
#pragma unroll
          for (int jj=0;jj<4;jj++){
            ULL kd = pk2(kvv[jj], kvv[jj]);
#pragma unroll
            for (int p=0;p<4;p++) FMA2(acc[jj][p], qp[p], kd, acc[jj][p]);
          }
        }
#pragma unroll
        for (int jj=0;jj<4;jj++)
#pragma unroll
          for (int p=0;p<4;p++){
            float2 v = upk(acc[jj][p]);
            v.x = __expf(0.25f * v.x);
            v.y = __expf(0.25f * v.y);
            *reinterpret_cast<ULL*>(att + (4*tx+jj)*128 + 8*ty + 2*p) = pk2(v.x, v.y);
          }
      }
      __syncthreads();

      // ---- partial row-sums over sk (contiguous reads) ----
      {
        const int sq = tid & 127, rg = tid >> 7;
        float smv = 0.f;
#pragma unroll 8
        for (int i2=0; i2<32; i2++) smv += att[(rg*32 + i2)*128 + sq];
        rs[rg*128 + sq] = smv;
      }
      __syncthreads();

      // ---- AV: o[dv][sq] = inv[sq] * sum_sk att[sk][sq]*v[dv][sk] ----
      {
        const int pg = tid & 31;        // sq tile of 4
        const int dq = (tid>>5) & 3;    // dv quad
        const int hf = tid >> 7;        // sk quarter
        const float* vb = qkv + (128 + hd*16 + 4*dq)*128;
        ULL a0r[4], a1r[4];
        ULL z = pk2(0.f,0.f);
#pragma unroll
        for (int r2=0;r2<4;r2++){ a0r[r2]=z; a1r[r2]=z; }
        for (int sk0 = hf*32; sk0 < hf*32 + 32; sk0 += 4){
          float4 v0 = *reinterpret_cast<const float4*>(vb + sk0);
          float4 v1 = *reinterpret_cast<const float4*>(vb + 128 + sk0);
          float4 v2 = *reinterpret_cast<const float4*>(vb + 256 + sk0);
          float4 v3 = *reinterpret_cast<const float4*>(vb + 384 + sk0);
          float vv[4][4] = {{v0.x,v0.y,v0.z,v0.w},{v1.x,v1.y,v1.z,v1.w},
                            {v2.x,v2.y,v2.z,v2.w},{v3.x,v3.y,v3.z,v3.w}};
#pragma unroll
          for (int s4=0; s4<4; s4++){
            float4 av = *reinterpret_cast<const float4*>(att + (sk0+s4)*128 + 4*pg);
            ULL a0 = pk2(av.x, av.y), a1 = pk2(av.z, av.w);
#pragma unroll
            for (int r2=0;r2<4;r2++){
              ULL vd = pk2(vv[r2][s4], vv[r2][s4]);
              FMA2(a0r[r2], a0, vd, a0r[r2]);
              FMA2(a1r[r2], a1, vd, a1r[r2]);
            }
          }
        }
        // local inverse of full row sums for our 4 sq
        float4 s0 = *reinterpret_cast<const float4*>(rs + 4*pg);
        float4 s1 = *reinterpret_cast<const float4*>(rs + 128 + 4*pg);
        float4 s2 = *reinterpret_cast<const float4*>(rs + 256 + 4*pg);
        float4 s3 = *reinterpret_cast<const float4*>(rs + 384 + 4*pg);
        float iv0 = 1.0f/(s0.x+s1.x+s2.x+s3.x);
        float iv1 = 1.0f/(s0.y+s1.y+s2.y+s3.y);
        float iv2 = 1.0f/(s0.z+s1.z+s2.z+s3.z);
        float iv3 = 1.0f/(s0.w+s1.w+s2.w+s3.w);
        ULL i0 = pk2(iv0, iv1), i1 = pk2(iv2, iv3);
        float* dst = (hf==0) ? (qkv + (hd*16 + 4*dq)*128)
                             : (aux + (hf-1)*2048 + 4*dq*128);
#pragma unroll
        for (int r2=0;r2<4;r2++){
          MUL2(a0r[r2], a0r[r2], i0);
          MUL2(a1r[r2], a1r[r2], i1);
          *reinterpret_cast<ULL*>(dst + r2*128 + 4*pg)     = a0r[r2];
          *reinterpret_cast<ULL*>(dst + r2*128 + 4*pg + 2) = a1r[r2];
        }
      }
      __syncthreads();

      // ---- combine sk-quarter partials into o ----
      {
        float4* ob = reinterpret_cast<float4*>(qkv + hd*16*128);
        const float4* p1 = reinterpret_cast<const float4*>(aux);
        const float4* p2 = reinterpret_cast<const float4*>(aux + 2048);
        const float4* p3 = reinterpret_cast<const float4*>(aux + 4096);
        float4 o = ob[tid], q1 = p1[tid], q2 = p2[tid], q3 = p3[tid];
        o.x += q1.x + q2.x + q3.x;
        o.y += q1.y + q2.y + q3.y;
        o.z += q1.z + q2.z + q3.z;
        o.w += q1.w + q2.w + q3.w;
        ob[tid] = o;
      }
      __syncthreads();
    }

    gemm_tok<64,64,false,2>(qkv, ow + l*64*64, obias + l*64, att, tid);
    __syncthreads();
    add_ln(h, att, l1s + l*64, l1b + l*64, aux, tid);
    __syncthreads();

    gemm_tok<128,64,true,2>(h, f1w + l*128*64, f1b + l*128, att, tid);
    __syncthreads();
    gemm_tok<64,128,false,2>(att, f2w + l*64*128, f2b + l*64, qkv, tid);
    __syncthreads();
    add_ln(h, qkv, l2s + l*64, l2b + l*64, aux, tid);
    __syncthreads();
  }

  // ---------------- Phase C: mean pool + head MLP ----------------
  {
    const int d = tid & 63, oc = tid >> 6;  // 8 groups of 16 tokens
    float s0 = 0.f;
#pragma unroll
    for (int t = oc*16; t < oc*16 + 16; t++) s0 += h[d*128 + t];
    aux[oc*64 + d] = s0;
  }
  __syncthreads();
  if (tid < 64){
    float hm = 0.f;
#pragma unroll
    for (int o2=0;o2<8;o2++) hm += aux[o2*64 + tid];
    aux[512 + tid] = hm * (1.0f/128.0f);
  }
  __syncthreads();
  if (tid < 32){
    float a = aux[512 + tid], c = aux[512 + 32 + tid];
    float sum = a + c, sq = a*a + c*c;
#pragma unroll
    for (int off=16; off; off>>=1){
      sum += __shfl_xor_sync(0xffffffffu, sum, off);
      sq  += __shfl_xor_sync(0xffffffffu, sq,  off);
    }
    if (tid == 0){
      float m = sum * (1.f/64.f);
      aux[576] = m;
      aux[577] = rsqrtf(sq * (1.f/64.f) - m*m + EPS_);
    }
  }
  __syncthreads();
  if (tid < 64){
    float m = aux[576], inv = aux[577];
    aux[640 + tid] = (aux[512+tid] - m)*inv*__ldg(hls+tid) + __ldg(hlb+tid);
  }
  __syncthreads();
  if (tid < 64){
    float acc = __ldg(h1b + tid);
#pragma unroll 8
    for (int k=0;k<64;k++) acc += aux[640+k]*__ldg(h1w + tid*64 + k);
    aux[704 + tid] = 0.5f*acc*(1.0f + erff(acc*0.70710678118654752f));
  }
  __syncthreads();
  if (tid < 3){
    float acc = __ldg(h2b + tid);
#pragma unroll 8
    for (int k=0;k<64;k++) acc += aux[704+k]*__ldg(h2w + tid*64 + k);
    out[b*3 + tid] = acc;
  }
}

extern "C" void kernel_launch(void* const* d_in, const int* in_sizes, int n_in,
                              void* d_out, int out_size)
{
  const int*   qli    = (const int*)  d_in[0];
  const int*   offs   = (const int*)  d_in[1];
  const float* coords = (const float*)d_in[2];
  const float* vals   = (const float*)d_in[3];
  const float* lg     = (const float*)d_in[4];
  const float* pw     = (const float*)d_in[5];
  const float* pb     = (const float*)d_in[6];
  const float* qw     = (const float*)d_in[7];
  const float* qb     = (const float*)d_in[8];
  const float* ow     = (const float*)d_in[9];
  const float* ob     = (const float*)d_in[10];
  const float* l1s    = (const float*)d_in[11];
  const float* l1b    = (const float*)d_in[12];
  const float* f1w    = (const float*)d_in[13];
  const float* f1b    = (const float*)d_in[14];
  const float* f2w    = (const float*)d_in[15];
  const float* f2b    = (const float*)d_in[16];
  const float* l2s    = (const float*)d_in[17];
  const float* l2b    = (const float*)d_in[18];
  const float* hls    = (const float*)d_in[19];
  const float* hlb    = (const float*)d_in[20];
  const float* h1w    = (const float*)d_in[21];
  const float* h1b    = (const float*)d_in[22];
  const float* h2w    = (const float*)d_in[23];
  const float* h2b    = (const float*)d_in[24];
  float* out = (float*)d_out;
  const int B = in_sizes[0];

  cudaFuncSetAttribute(ff_kernel, cudaFuncAttributeMaxDynamicSharedMemorySize,
                       SMEM_FLOATS * (int)sizeof(float));
  ff_kernel<<<B, 512, SMEM_FLOATS * sizeof(float)>>>(
      qli, offs, coords, vals, lg, pw, pb, qw, qb, ow, ob,
      l1s, l1b, f1w, f1b, f2w, f2b, l2s, l2b,
      hls, hlb, h1w, h1b, h2w, h2b, out);
}

// round 6
// speedup vs baseline: 1.5966x; 1.1590x over previous
#include <cuda_runtime.h>

typedef unsigned long long ULL;

__device__ __forceinline__ ULL pk2(float lo, float hi){
  ULL r; asm("mov.b64 %0, {%1,%2};" : "=l"(r) : "f"(lo), "f"(hi)); return r;
}
__device__ __forceinline__ float2 upk(ULL v){
  float2 r; asm("mov.b64 {%0,%1}, %2;" : "=f"(r.x), "=f"(r.y) : "l"(v)); return r;
}
#define FMA2(d,a,bb,c) asm("fma.rn.f32x2 %0, %1, %2, %3;" : "=l"(d) : "l"(a), "l"(bb), "l"(c))
#define MUL2(d,a,bb)   asm("mul.rn.f32x2 %0, %1, %2;"     : "=l"(d) : "l"(a), "l"(bb))

constexpr int NX_ = 128, NY_ = 128, NT_ = 64;
constexpr float EPS_ = 1e-5f;

constexpr int OFF_H   = 0;         // h[64][128]
constexpr int OFF_QKV = 8192;      // qkv[192][128]; also ff1 W (first 8192) + ff2 W (next 8192)
constexpr int OFF_ATT = 32768;     // att[128][128]; also staged qkv W (12288)
constexpr int OFF_AUX = 49152;     // AV partials / LN scratch / staged out W (4096)
constexpr int OFF_RS  = 55296;     // 512 rowsum partials
constexpr int SMEM_FLOATS = 55808; // 223,232 bytes

__device__ __forceinline__ void stage(float* __restrict__ dst,
                                      const float* __restrict__ src,
                                      int n4, int tid)
{
  const float4* s = reinterpret_cast<const float4*>(src);
  float4* d = reinterpret_cast<float4*>(dst);
  for (int i = tid; i < n4; i += 512) d[i] = s[i];
}

// C[o][s] = act( sum_k A[k][s]*Ws[o*K+k] + Bv[o] ); Ws in SHARED (uniform broadcast reads)
template<int OUT, int K, bool RELU, int TPT>
__device__ __forceinline__ void gemm_sm(const float* __restrict__ A,
                                        const float* __restrict__ Ws,
                                        const float* __restrict__ Bv,
                                        float* __restrict__ C, int tid)
{
  constexpr int NTG = 128/TPT;
  constexpr int NOG = 512/NTG;
  constexpr int TO  = OUT/NOG;
  constexpr int PU  = TPT/2;
  const int tx  = tid & (NTG-1);
  const int g   = tid / NTG;        // warp-uniform
  const int tok = TPT*tx;
  ULL acc[TO][PU];
#pragma unroll
  for (int j=0;j<TO;j++){
    float b = __ldg(Bv + g*TO + j);
    ULL bb = pk2(b,b);
#pragma unroll
    for (int p=0;p<PU;p++) acc[j][p] = bb;
  }
#pragma unroll 2
  for (int k=0;k<K;k+=4){
    ULL a0[PU], a1[PU], a2[PU], a3[PU];
#pragma unroll
    for (int p=0;p<PU;p++){
      a0[p] = *reinterpret_cast<const ULL*>(A + (k  )*128 + tok + 2*p);
      a1[p] = *reinterpret_cast<const ULL*>(A + (k+1)*128 + tok + 2*p);
      a2[p] = *reinterpret_cast<const ULL*>(A + (k+2)*128 + tok + 2*p);
      a3[p] = *reinterpret_cast<const ULL*>(A + (k+3)*128 + tok + 2*p);
    }
#pragma unroll
    for (int j=0;j<TO;j++){
      float4 w = *reinterpret_cast<const float4*>(Ws + (g*TO+j)*K + k);
      ULL w0 = pk2(w.x,w.x), w1 = pk2(w.y,w.y), w2 = pk2(w.z,w.z), w3 = pk2(w.w,w.w);
#pragma unroll
      for (int p=0;p<PU;p++){
        FMA2(acc[j][p], a0[p], w0, acc[j][p]);
        FMA2(acc[j][p], a1[p], w1, acc[j][p]);
        FMA2(acc[j][p], a2[p], w2, acc[j][p]);
        FMA2(acc[j][p], a3[p], w3, acc[j][p]);
      }
    }
  }
#pragma unroll
  for (int j=0;j<TO;j++){
#pragma unroll
    for (int p=0;p<PU;p++){
      float2 v = upk(acc[j][p]);
      if (RELU){ v.x = fmaxf(v.x,0.f); v.y = fmaxf(v.y,0.f); }
      *reinterpret_cast<float2*>(C + (g*TO+j)*128 + tok + 2*p) = v;
    }
  }
}

// h = LN(h + r), with up to two staging jobs overlapped into pass 1
__device__ __forceinline__ void add_ln(float* __restrict__ h,
                                       const float* __restrict__ r,
                                       const float* __restrict__ gs,
                                       const float* __restrict__ gb,
                                       float* __restrict__ aux, int tid,
                                       float* wdst0 = nullptr, const float* wsrc0 = nullptr, int n40 = 0,
                                       float* wdst1 = nullptr, const float* wsrc1 = nullptr, int n41 = 0)
{
  const int s = tid & 127, g = tid >> 7;
  float sum=0.f, sq=0.f;
#pragma unroll
  for (int d=16*g; d<16*g+16; d++){
    float x = h[d*128+s] + r[d*128+s];
    h[d*128+s] = x;
    sum += x; sq += x*x;
  }
  aux[g*128+s] = sum;
  aux[512 + g*128+s] = sq;
  if (wsrc0) stage(wdst0, wsrc0, n40, tid);
  if (wsrc1) stage(wdst1, wsrc1, n41, tid);
  __syncthreads();
  if (tid < 128){
    float S = aux[tid] + aux[128+tid] + aux[256+tid] + aux[384+tid];
    float Q = aux[512+tid] + aux[640+tid] + aux[768+tid] + aux[896+tid];
    float m = S * (1.f/64.f);
    float inv = rsqrtf(Q * (1.f/64.f) - m*m + EPS_);
    aux[1024+tid] = m;
    aux[1152+tid] = inv;
  }
  __syncthreads();
  {
    float m = aux[1024+s], inv = aux[1152+s];
#pragma unroll
    for (int d=16*g; d<16*g+16; d++){
      h[d*128+s] = (h[d*128+s] - m)*inv*__ldg(gs+d) + __ldg(gb+d);
    }
  }
}

__device__ __forceinline__ float dper(float diff, float L){
  float m = fmodf(diff + 0.5f*L, L);
  if (m < 0.f) m += L;
  return m - 0.5f*L;
}

__global__ void __launch_bounds__(512, 1)
ff_kernel(const int* __restrict__ q_lin_idx, const int* __restrict__ offs,
          const float* __restrict__ coords, const float* __restrict__ vals,
          const float* __restrict__ lg,
          const float* __restrict__ pw, const float* __restrict__ pb,
          const float* __restrict__ qw, const float* __restrict__ qbias,
          const float* __restrict__ ow, const float* __restrict__ obias,
          const float* __restrict__ l1s, const float* __restrict__ l1b,
          const float* __restrict__ f1w, const float* __restrict__ f1b,
          const float* __restrict__ f2w, const float* __restrict__ f2b,
          const float* __restrict__ l2s, const float* __restrict__ l2b,
          const float* __restrict__ hls, const float* __restrict__ hlb,
          const float* __restrict__ h1w, const float* __restrict__ h1b,
          const float* __restrict__ h2w, const float* __restrict__ h2b,
          float* __restrict__ out)
{
  extern __shared__ float sm[];
  float* h    = sm + OFF_H;
  float* qkv  = sm + OFF_QKV;
  float* att  = sm + OFF_ATT;
  float* aux  = sm + OFF_AUX;
  float* rs   = sm + OFF_RS;

  const int tid = threadIdx.x;
  const int b   = blockIdx.x;

  // ---------------- Phase A: gather + input projection (+ stage layer-0 qkv W) ----------------
  {
    const int s = tid & 127, g = tid >> 7;
    int qi = __ldg(q_lin_idx + b);
    int i  = qi >> 13;
    int rr = qi & 8191;
    int j  = rr >> 6;
    int kk = rr & 63;
    int di = __ldg(offs + 3*s), dj = __ldg(offs + 3*s + 1), dk = __ldg(offs + 3*s + 2);
    int I = (i + di) & (NX_-1);
    int J = (j + dj) & (NY_-1);
    int T = min(max(kk + dk, 0), NT_-1);
    int nb = (I << 13) + (J << 6) + T;
    float qx = __ldg(coords + 3*qi), qy = __ldg(coords + 3*qi + 1), qt = __ldg(coords + 3*qi + 2);
    float nx = __ldg(coords + 3*nb), ny = __ldg(coords + 3*nb + 1), nt = __ldg(coords + 3*nb + 2);
    float g0 = expf(__ldg(lg+0)), g1 = expf(__ldg(lg+1)), g2 = expf(__ldg(lg+2));
    float f0 = dper(nx - qx, 2.0f) * g0;
    float f1 = dper(ny - qy, 2.0f) * g1;
    float f2 = (nt - qt) * g2;
    float f3 = __ldg(vals + 3*nb), f4 = __ldg(vals + 3*nb + 1), f5 = __ldg(vals + 3*nb + 2);
#pragma unroll
    for (int d = g*16; d < g*16 + 16; d++){
      float a = __ldg(pb + d);
      a += __ldg(pw + 6*d + 0)*f0 + __ldg(pw + 6*d + 1)*f1 + __ldg(pw + 6*d + 2)*f2
         + __ldg(pw + 6*d + 3)*f3 + __ldg(pw + 6*d + 4)*f4 + __ldg(pw + 6*d + 5)*f5;
      h[d*128 + s] = a;
    }
    stage(att, qw, 12288/4, tid);
  }
  __syncthreads();

  // ---------------- Phase B: 2 transformer layers ----------------
  for (int l = 0; l < 2; l++){
    gemm_sm<192,64,false,4>(h, att, qbias + l*192, qkv, tid);
    __syncthreads();

    for (int hd = 0; hd < 4; hd++){
      // QK^T + fused exp
      {
        const float* qb2 = qkv + (hd*16)*128;
        const float* kb  = qkv + (64 + hd*16)*128;
        const int tx = tid & 31;
        const int ty = tid >> 5;
        ULL acc[4][4];
        ULL z = pk2(0.f, 0.f);
#pragma unroll
        for (int jj=0;jj<4;jj++)
#pragma unroll
          for (int p=0;p<4;p++) acc[jj][p] = z;
#pragma unroll 4
        for (int di=0; di<16; di++){
          ULL qp[4];
#pragma unroll
          for (int p=0;p<4;p++)
            qp[p] = *reinterpret_cast<const ULL*>(qb2 + di*128 + 8*ty + 2*p);
          float4 kf = *reinterpret_cast<const float4*>(kb + di*128 + 4*tx);
          float kvv[4] = {kf.x, kf.y, kf.z, kf.w};
#pragma unroll
          for (int jj=0;jj<4;jj++){
            ULL kd = pk2(kvv[jj], kvv[jj]);
#pragma unroll
            for (int p=0;p<4;p++) FMA2(acc[jj][p], qp[p], kd, acc[jj][p]);
          }
        }
#pragma unroll
        for (int jj=0;jj<4;jj++)
#pragma unroll
          for (int p=0;p<4;p++){
            float2 v = upk(acc[jj][p]);
            v.x = __expf(0.25f * v.x);
            v.y = __expf(0.25f * v.y);
            *reinterpret_cast<ULL*>(att + (4*tx+jj)*128 + 8*ty + 2*p) = pk2(v.x, v.y);
          }
      }
      __syncthreads();

      // partial row-sums
      {
        const int sq = tid & 127, rg = tid >> 7;
        float smv = 0.f;
#pragma unroll 8
        for (int i2=0; i2<32; i2++) smv += att[(rg*32 + i2)*128 + sq];
        rs[rg*128 + sq] = smv;
      }
      __syncthreads();

      // AV
      {
        const int pg = tid & 31;
        const int dq = (tid>>5) & 3;
        const int hf = tid >> 7;
        const float* vb = qkv + (128 + hd*16 + 4*dq)*128;
        ULL a0r[4], a1r[4];
        ULL z = pk2(0.f,0.f);
#pragma unroll
        for (int r2=0;r2<4;r2++){ a0r[r2]=z; a1r[r2]=z; }
        for (int sk0 = hf*32; sk0 < hf*32 + 32; sk0 += 4){
          float4 v0 = *reinterpret_cast<const float4*>(vb + sk0);
          float4 v1 = *reinterpret_cast<const float4*>(vb + 128 + sk0);
          float4 v2 = *reinterpret_cast<const float4*>(vb + 256 + sk0);
          float4 v3 = *reinterpret_cast<const float4*>(vb + 384 + sk0);
          float vv[4][4] = {{v0.x,v0.y,v0.z,v0.w},{v1.x,v1.y,v1.z,v1.w},
                            {v2.x,v2.y,v2.z,v2.w},{v3.x,v3.y,v3.z,v3.w}};
#pragma unroll
          for (int s4=0; s4<4; s4++){
            float4 av = *reinterpret_cast<const float4*>(att + (sk0+s4)*128 + 4*pg);
            ULL a0 = pk2(av.x, av.y), a1 = pk2(av.z, av.w);
#pragma unroll
            for (int r2=0;r2<4;r2++){
              ULL vd = pk2(vv[r2][s4], vv[r2][s4]);
              FMA2(a0r[r2], a0, vd, a0r[r2]);
              FMA2(a1r[r2], a1, vd, a1r[r2]);
            }
          }
        }
        float4 s0 = *reinterpret_cast<const float4*>(rs + 4*pg);
        float4 s1 = *reinterpret_cast<const float4*>(rs + 128 + 4*pg);
        float4 s2 = *reinterpret_cast<const float4*>(rs + 256 + 4*pg);
        float4 s3 = *reinterpret_cast<const float4*>(rs + 384 + 4*pg);
        float iv0 = 1.0f/(s0.x+s1.x+s2.x+s3.x);
        float iv1 = 1.0f/(s0.y+s1.y+s2.y+s3.y);
        float iv2 = 1.0f/(s0.z+s1.z+s2.z+s3.z);
        float iv3 = 1.0f/(s0.w+s1.w+s2.w+s3.w);
        ULL i0 = pk2(iv0, iv1), i1 = pk2(iv2, iv3);
        float* dst = (hf==0) ? (qkv + (hd*16 + 4*dq)*128)
                             : (aux + (hf-1)*2048 + 4*dq*128);
#pragma unroll
        for (int r2=0;r2<4;r2++){
          MUL2(a0r[r2], a0r[r2], i0);
          MUL2(a1r[r2], a1r[r2], i1);
          *reinterpret_cast<ULL*>(dst + r2*128 + 4*pg)     = a0r[r2];
          *reinterpret_cast<ULL*>(dst + r2*128 + 4*pg + 2) = a1r[r2];
        }
      }
      __syncthreads();

      // combine
      {
        float4* ob = reinterpret_cast<float4*>(qkv + hd*16*128);
        const float4* p1 = reinterpret_cast<const float4*>(aux);
        const float4* p2 = reinterpret_cast<const float4*>(aux + 2048);
        const float4* p3 = reinterpret_cast<const float4*>(aux + 4096);
        float4 o = ob[tid], q1 = p1[tid], q2 = p2[tid], q3 = p3[tid];
        o.x += q1.x + q2.x + q3.x;
        o.y += q1.y + q2.y + q3.y;
        o.z += q1.z + q2.z + q3.z;
        o.w += q1.w + q2.w + q3.w;
        ob[tid] = o;
      }
      __syncthreads();
    }

    // stage out W into aux, out gemm into att
    stage(aux, ow + l*64*64, 4096/4, tid);
    __syncthreads();
    gemm_sm<64,64,false,2>(qkv, aux, obias + l*64, att, tid);
    __syncthreads();
    // add_ln with overlapped staging of ff1 W -> qkv[0..8192) and ff2 W -> qkv[8192..16384)
    add_ln(h, att, l1s + l*64, l1b + l*64, aux, tid,
           qkv,        f1w + l*128*64, 8192/4,
           qkv + 8192, f2w + l*64*128, 8192/4);
    __syncthreads();
    gemm_sm<128,64,true,2>(h, qkv, f1b + l*128, att, tid);
    __syncthreads();
    gemm_sm<64,128,false,2>(att, qkv + 8192, f2b + l*64, qkv, tid);
    __syncthreads();
    if (l == 0){
      add_ln(h, qkv, l2s, l2b, aux, tid, att, qw + 12288, 12288/4);
    } else {
      add_ln(h, qkv, l2s + 64, l2b + 64, aux, tid);
    }
    __syncthreads();
  }

  // ---------------- Phase C ----------------
  {
    const int d = tid & 63, oc = tid >> 6;
    float s0 = 0.f;
#pragma unroll
    for (int t = oc*16; t < oc*16 + 16; t++) s0 += h[d*128 + t];
    aux[oc*64 + d] = s0;
  }
  __syncthreads();
  if (tid < 64){
    float hm = 0.f;
#pragma unroll
    for (int o2=0;o2<8;o2++) hm += aux[o2*64 + tid];
    aux[512 + tid] = hm * (1.0f/128.0f);
  }
  __syncthreads();
  if (tid < 32){
    float a = aux[512 + tid], c = aux[512 + 32 + tid];
    float sum = a + c, sq = a*a + c*c;
#pragma unroll
    for (int off=16; off; off>>=1){
      sum += __shfl_xor_sync(0xffffffffu, sum, off);
      sq  += __shfl_xor_sync(0xffffffffu, sq,  off);
    }
    if (tid == 0){
      float m = sum * (1.f/64.f);
      aux[576] = m;
      aux[577] = rsqrtf(sq * (1.f/64.f) - m*m + EPS_);
    }
  }
  __syncthreads();
  if (tid < 64){
    float m = aux[576], inv = aux[577];
    aux[640 + tid] = (aux[512+tid] - m)*inv*__ldg(hls+tid) + __ldg(hlb+tid);
  }
  __syncthreads();
  if (tid < 64){
    float acc = __ldg(h1b + tid);
#pragma unroll 8
    for (int k=0;k<64;k++) acc += aux[640+k]*__ldg(h1w + tid*64 + k);
    aux[704 + tid] = 0.5f*acc*(1.0f + erff(acc*0.70710678118654752f));
  }
  __syncthreads();
  if (tid < 3){
    float acc = __ldg(h2b + tid);
#pragma unroll 8
    for (int k=0;k<64;k++) acc += aux[704+k]*__ldg(h2w + tid*64 + k);
    out[b*3 + tid] = acc;
  }
}

extern "C" void kernel_launch(void* const* d_in, const int* in_sizes, int n_in,
                              void* d_out, int out_size)
{
  const int*   qli    = (const int*)  d_in[0];
  const int*   offs   = (const int*)  d_in[1];
  const float* coords = (const float*)d_in[2];
  const float* vals   = (const float*)d_in[3];
  const float* lg     = (const float*)d_in[4];
  const float* pw     = (const float*)d_in[5];
  const float* pb     = (const float*)d_in[6];
  const float* qw     = (const float*)d_in[7];
  const float* qb     = (const float*)d_in[8];
  const float* ow     = (const float*)d_in[9];
  const float* ob     = (const float*)d_in[10];
  const float* l1s    = (const float*)d_in[11];
  const float* l1b    = (const float*)d_in[12];
  const float* f1w    = (const float*)d_in[13];
  const float* f1b    = (const float*)d_in[14];
  const float* f2w    = (const float*)d_in[15];
  const float* f2b    = (const float*)d_in[16];
  const float* l2s    = (const float*)d_in[17];
  const float* l2b    = (const float*)d_in[18];
  const float* hls    = (const float*)d_in[19];
  const float* hlb    = (const float*)d_in[20];
  const float* h1w    = (const float*)d_in[21];
  const float* h1b    = (const float*)d_in[22];
  const float* h2w    = (const float*)d_in[23];
  const float* h2b    = (const float*)d_in[24];
  float* out = (float*)d_out;
  const int B = in_sizes[0];

  cudaFuncSetAttribute(ff_kernel, cudaFuncAttributeMaxDynamicSharedMemorySize,
                       SMEM_FLOATS * (int)sizeof(float));
  ff_kernel<<<B, 512, SMEM_FLOATS * sizeof(float)>>>(
      qli, offs, coords, vals, lg, pw, pb, qw, qb, ow, ob,
      l1s, l1b, f1w, f1b, f2w, f2b, l2s, l2b,
      hls, hlb, h1w, h1b, h2w, h2b, out);
}

// round 7
// speedup vs baseline: 1.7754x; 1.1120x over previous
#include <cuda_runtime.h>

typedef unsigned long long ULL;

__device__ __forceinline__ ULL pk2(float lo, float hi){
  ULL r; asm("mov.b64 %0, {%1,%2};" : "=l"(r) : "f"(lo), "f"(hi)); return r;
}
__device__ __forceinline__ float2 upk(ULL v){
  float2 r; asm("mov.b64 {%0,%1}, %2;" : "=f"(r.x), "=f"(r.y) : "l"(v)); return r;
}
#define FMA2(d,a,bb,c) asm("fma.rn.f32x2 %0, %1, %2, %3;" : "=l"(d) : "l"(a), "l"(bb), "l"(c))
#define MUL2(d,a,bb)   asm("mul.rn.f32x2 %0, %1, %2;"     : "=l"(d) : "l"(a), "l"(bb))

constexpr int NX_ = 128, NY_ = 128, NT_ = 64;
constexpr float EPS_ = 1e-5f;

constexpr int OFF_H   = 0;         // h[64][128]
constexpr int OFF_QKV = 8192;      // qkv[192][128]; also ff1 W (8192) + ff2 W (8192)
constexpr int OFF_ATT = 32768;     // att[128][128]; also staged qkv W (12288)
constexpr int OFF_AUX = 49152;     // AV partials / LN scratch / staged out W (4096)
constexpr int OFF_RS  = 55296;     // 512 rowsum partials
constexpr int SMEM_FLOATS = 55808; // 223,232 bytes

__device__ __forceinline__ void stage(float* __restrict__ dst,
                                      const float* __restrict__ src,
                                      int n4, int tid)
{
  const float4* s = reinterpret_cast<const float4*>(src);
  float4* d = reinterpret_cast<float4*>(dst);
  for (int i = tid; i < n4; i += 512) d[i] = s[i];
}

// C[o][s] = act( sum_k A[k][s]*Ws[o*K+k] + Bv[o] ); Ws in SHARED (uniform broadcast reads)
template<int OUT, int K, bool RELU, int TPT>
__device__ __forceinline__ void gemm_sm(const float* __restrict__ A,
                                        const float* __restrict__ Ws,
                                        const float* __restrict__ Bv,
                                        float* __restrict__ C, int tid)
{
  constexpr int NTG = 128/TPT;
  constexpr int NOG = 512/NTG;
  constexpr int TO  = OUT/NOG;
  constexpr int PU  = TPT/2;
  const int tx  = tid & (NTG-1);
  const int g   = tid / NTG;        // warp-uniform
  const int tok = TPT*tx;
  ULL acc[TO][PU];
#pragma unroll
  for (int j=0;j<TO;j++){
    float b = __ldg(Bv + g*TO + j);
    ULL bb = pk2(b,b);
#pragma unroll
    for (int p=0;p<PU;p++) acc[j][p] = bb;
  }
#pragma unroll 2
  for (int k=0;k<K;k+=4){
    ULL a0[PU], a1[PU], a2[PU], a3[PU];
    if (TPT == 4){
      float4 f0 = *reinterpret_cast<const float4*>(A + (k  )*128 + tok);
      float4 f1 = *reinterpret_cast<const float4*>(A + (k+1)*128 + tok);
      float4 f2 = *reinterpret_cast<const float4*>(A + (k+2)*128 + tok);
      float4 f3 = *reinterpret_cast<const float4*>(A + (k+3)*128 + tok);
      a0[0]=pk2(f0.x,f0.y); a0[PU-1]=pk2(f0.z,f0.w);
      a1[0]=pk2(f1.x,f1.y); a1[PU-1]=pk2(f1.z,f1.w);
      a2[0]=pk2(f2.x,f2.y); a2[PU-1]=pk2(f2.z,f2.w);
      a3[0]=pk2(f3.x,f3.y); a3[PU-1]=pk2(f3.z,f3.w);
    } else {
#pragma unroll
      for (int p=0;p<PU;p++){
        a0[p] = *reinterpret_cast<const ULL*>(A + (k  )*128 + tok + 2*p);
        a1[p] = *reinterpret_cast<const ULL*>(A + (k+1)*128 + tok + 2*p);
        a2[p] = *reinterpret_cast<const ULL*>(A + (k+2)*128 + tok + 2*p);
        a3[p] = *reinterpret_cast<const ULL*>(A + (k+3)*128 + tok + 2*p);
      }
    }
#pragma unroll
    for (int j=0;j<TO;j++){
      float4 w = *reinterpret_cast<const float4*>(Ws + (g*TO+j)*K + k);
      ULL w0 = pk2(w.x,w.x), w1 = pk2(w.y,w.y), w2 = pk2(w.z,w.z), w3 = pk2(w.w,w.w);
#pragma unroll
      for (int p=0;p<PU;p++){
        FMA2(acc[j][p], a0[p], w0, acc[j][p]);
        FMA2(acc[j][p], a1[p], w1, acc[j][p]);
        FMA2(acc[j][p], a2[p], w2, acc[j][p]);
        FMA2(acc[j][p], a3[p], w3, acc[j][p]);
      }
    }
  }
#pragma unroll
  for (int j=0;j<TO;j++){
    if (TPT == 4){
      float2 v0 = upk(acc[j][0]);
      float2 v1 = upk(acc[j][PU-1]);
      if (RELU){
        v0.x=fmaxf(v0.x,0.f); v0.y=fmaxf(v0.y,0.f);
        v1.x=fmaxf(v1.x,0.f); v1.y=fmaxf(v1.y,0.f);
      }
      *reinterpret_cast<float4*>(C + (g*TO+j)*128 + tok) = make_float4(v0.x,v0.y,v1.x,v1.y);
    } else {
#pragma unroll
      for (int p=0;p<PU;p++){
        float2 v = upk(acc[j][p]);
        if (RELU){ v.x = fmaxf(v.x,0.f); v.y = fmaxf(v.y,0.f); }
        *reinterpret_cast<float2*>(C + (g*TO+j)*128 + tok + 2*p) = v;
      }
    }
  }
}

// h = LN(h + r), with up to two staging jobs overlapped into pass 1
__device__ __forceinline__ void add_ln(float* __restrict__ h,
                                       const float* __restrict__ r,
                                       const float* __restrict__ gs,
                                       const float* __restrict__ gb,
                                       float* __restrict__ aux, int tid,
                                       float* wdst0 = nullptr, const float* wsrc0 = nullptr, int n40 = 0,
                                       float* wdst1 = nullptr, const float* wsrc1 = nullptr, int n41 = 0)
{
  const int s = tid & 127, g = tid >> 7;
  float sum=0.f, sq=0.f;
#pragma unroll
  for (int d=16*g; d<16*g+16; d++){
    float x = h[d*128+s] + r[d*128+s];
    h[d*128+s] = x;
    sum += x; sq += x*x;
  }
  aux[g*128+s] = sum;
  aux[512 + g*128+s] = sq;
  if (wsrc0) stage(wdst0, wsrc0, n40, tid);
  if (wsrc1) stage(wdst1, wsrc1, n41, tid);
  __syncthreads();
  if (tid < 128){
    float S = aux[tid] + aux[128+tid] + aux[256+tid] + aux[384+tid];
    float Q = aux[512+tid] + aux[640+tid] + aux[768+tid] + aux[896+tid];
    float m = S * (1.f/64.f);
    float inv = rsqrtf(Q * (1.f/64.f) - m*m + EPS_);
    aux[1024+tid] = m;
    aux[1152+tid] = inv;
  }
  __syncthreads();
  {
    float m = aux[1024+s], inv = aux[1152+s];
#pragma unroll
    for (int d=16*g; d<16*g+16; d++){
      h[d*128+s] = (h[d*128+s] - m)*inv*__ldg(gs+d) + __ldg(gb+d);
    }
  }
}

__device__ __forceinline__ float dper(float diff, float L){
  float m = fmodf(diff + 0.5f*L, L);
  if (m < 0.f) m += L;
  return m - 0.5f*L;
}

__global__ void __launch_bounds__(512, 1)
ff_kernel(const int* __restrict__ q_lin_idx, const int* __restrict__ offs,
          const float* __restrict__ coords, const float* __restrict__ vals,
          const float* __restrict__ lg,
          const float* __restrict__ pw, const float* __restrict__ pb,
          const float* __restrict__ qw, const float* __restrict__ qbias,
          const float* __restrict__ ow, const float* __restrict__ obias,
          const float* __restrict__ l1s, const float* __restrict__ l1b,
          const float* __restrict__ f1w, const float* __restrict__ f1b,
          const float* __restrict__ f2w, const float* __restrict__ f2b,
          const float* __restrict__ l2s, const float* __restrict__ l2b,
          const float* __restrict__ hls, const float* __restrict__ hlb,
          const float* __restrict__ h1w, const float* __restrict__ h1b,
          const float* __restrict__ h2w, const float* __restrict__ h2b,
          float* __restrict__ out)
{
  extern __shared__ float sm[];
  float* h    = sm + OFF_H;
  float* qkv  = sm + OFF_QKV;
  float* att  = sm + OFF_ATT;
  float* aux  = sm + OFF_AUX;
  float* rs   = sm + OFF_RS;

  const int tid = threadIdx.x;
  const int b   = blockIdx.x;

  // ---------------- Phase A: gather + input projection (+ stage layer-0 qkv W) ----------------
  {
    const int s = tid & 127, g = tid >> 7;
    int qi = __ldg(q_lin_idx + b);
    int i  = qi >> 13;
    int rr = qi & 8191;
    int j  = rr >> 6;
    int kk = rr & 63;
    int di = __ldg(offs + 3*s), dj = __ldg(offs + 3*s + 1), dk = __ldg(offs + 3*s + 2);
    int I = (i + di) & (NX_-1);
    int J = (j + dj) & (NY_-1);
    int T = min(max(kk + dk, 0), NT_-1);
    int nb = (I << 13) + (J << 6) + T;
    float qx = __ldg(coords + 3*qi), qy = __ldg(coords + 3*qi + 1), qt = __ldg(coords + 3*qi + 2);
    float nx = __ldg(coords + 3*nb), ny = __ldg(coords + 3*nb + 1), nt = __ldg(coords + 3*nb + 2);
    float g0 = expf(__ldg(lg+0)), g1 = expf(__ldg(lg+1)), g2 = expf(__ldg(lg+2));
    float f0 = dper(nx - qx, 2.0f) * g0;
    float f1 = dper(ny - qy, 2.0f) * g1;
    float f2 = (nt - qt) * g2;
    float f3 = __ldg(vals + 3*nb), f4 = __ldg(vals + 3*nb + 1), f5 = __ldg(vals + 3*nb + 2);
#pragma unroll
    for (int d = g*16; d < g*16 + 16; d++){
      float a = __ldg(pb + d);
      a += __ldg(pw + 6*d + 0)*f0 + __ldg(pw + 6*d + 1)*f1 + __ldg(pw + 6*d + 2)*f2
         + __ldg(pw + 6*d + 3)*f3 + __ldg(pw + 6*d + 4)*f4 + __ldg(pw + 6*d + 5)*f5;
      h[d*128 + s] = a;
    }
    stage(att, qw, 12288/4, tid);
  }
  __syncthreads();

  // ---------------- Phase B: 2 transformer layers ----------------
  for (int l = 0; l < 2; l++){
    gemm_sm<192,64,false,4>(h, att, qbias + l*192, qkv, tid);
    __syncthreads();

    for (int hd = 0; hd < 4; hd++){
      // ---- QK^T + fused exp: att[sk][sq] = exp(0.25*q.k)
      //      lanes -> sq (contiguous), warps -> sk (uniform); conflict-free ----
      {
        const float* qb2 = qkv + (hd*16)*128;
        const float* kb  = qkv + (64 + hd*16)*128;
        const int tx = tid & 31;   // sq tile of 4 (lane-contiguous)
        const int ty = tid >> 5;   // sk tile of 8 (warp-uniform)
        ULL acc[8][2];
        ULL z = pk2(0.f, 0.f);
#pragma unroll
        for (int jj=0;jj<8;jj++){ acc[jj][0]=z; acc[jj][1]=z; }
#pragma unroll 4
        for (int di=0; di<16; di++){
          float4 qf = *reinterpret_cast<const float4*>(qb2 + di*128 + 4*tx);
          ULL q0 = pk2(qf.x,qf.y), q1 = pk2(qf.z,qf.w);
          float4 k0 = *reinterpret_cast<const float4*>(kb + di*128 + 8*ty);
          float4 k1 = *reinterpret_cast<const float4*>(kb + di*128 + 8*ty + 4);
          float kvv[8] = {k0.x,k0.y,k0.z,k0.w,k1.x,k1.y,k1.z,k1.w};
#pragma unroll
          for (int jj=0;jj<8;jj++){
            ULL kd = pk2(kvv[jj], kvv[jj]);
            FMA2(acc[jj][0], q0, kd, acc[jj][0]);
            FMA2(acc[jj][1], q1, kd, acc[jj][1]);
          }
        }
#pragma unroll
        for (int jj=0;jj<8;jj++){
          float2 v0 = upk(acc[jj][0]);
          float2 v1 = upk(acc[jj][1]);
          float4 e;
          e.x = __expf(0.25f * v0.x);
          e.y = __expf(0.25f * v0.y);
          e.z = __expf(0.25f * v1.x);
          e.w = __expf(0.25f * v1.y);
          *reinterpret_cast<float4*>(att + (8*ty+jj)*128 + 4*tx) = e;
        }
      }
      __syncthreads();

      // ---- partial row-sums over sk ----
      {
        const int sq = tid & 127, rg = tid >> 7;
        float smv = 0.f;
#pragma unroll 8
        for (int i2=0; i2<32; i2++) smv += att[(rg*32 + i2)*128 + sq];
        rs[rg*128 + sq] = smv;
      }
      __syncthreads();

      // ---- AV ----
      {
        const int pg = tid & 31;
        const int dq = (tid>>5) & 3;
        const int hf = tid >> 7;
        const float* vb = qkv + (128 + hd*16 + 4*dq)*128;
        ULL a0r[4], a1r[4];
        ULL z = pk2(0.f,0.f);
#pragma unroll
        for (int r2=0;r2<4;r2++){ a0r[r2]=z; a1r[r2]=z; }
        for (int sk0 = hf*32; sk0 < hf*32 + 32; sk0 += 4){
          float4 v0 = *reinterpret_cast<const float4*>(vb + sk0);
          float4 v1 = *reinterpret_cast<const float4*>(vb + 128 + sk0);
          float4 v2 = *reinterpret_cast<const float4*>(vb + 256 + sk0);
          float4 v3 = *reinterpret_cast<const float4*>(vb + 384 + sk0);
          float vv[4][4] = {{v0.x,v0.y,v0.z,v0.w},{v1.x,v1.y,v1.z,v1.w},
                            {v2.x,v2.y,v2.z,v2.w},{v3.x,v3.y,v3.z,v3.w}};
#pragma unroll
          for (int s4=0; s4<4; s4++){
            float4 av = *reinterpret_cast<const float4*>(att + (sk0+s4)*128 + 4*pg);
            ULL a0 = pk2(av.x, av.y), a1 = pk2(av.z, av.w);
#pragma unroll
            for (int r2=0;r2<4;r2++){
              ULL vd = pk2(vv[r2][s4], vv[r2][s4]);
              FMA2(a0r[r2], a0, vd, a0r[r2]);
              FMA2(a1r[r2], a1, vd, a1r[r2]);
            }
          }
        }
        float4 s0 = *reinterpret_cast<const float4*>(rs + 4*pg);
        float4 s1 = *reinterpret_cast<const float4*>(rs + 128 + 4*pg);
        float4 s2 = *reinterpret_cast<const float4*>(rs + 256 + 4*pg);
        float4 s3 = *reinterpret_cast<const float4*>(rs + 384 + 4*pg);
        float iv0 = 1.0f/(s0.x+s1.x+s2.x+s3.x);
        float iv1 = 1.0f/(s0.y+s1.y+s2.y+s3.y);
        float iv2 = 1.0f/(s0.z+s1.z+s2.z+s3.z);
        float iv3 = 1.0f/(s0.w+s1.w+s2.w+s3.w);
        ULL i0 = pk2(iv0, iv1), i1 = pk2(iv2, iv3);
        float* dst = (hf==0) ? (qkv + (hd*16 + 4*dq)*128)
                             : (aux + (hf-1)*2048 + 4*dq*128);
#pragma unroll
        for (int r2=0;r2<4;r2++){
          MUL2(a0r[r2], a0r[r2], i0);
          MUL2(a1r[r2], a1r[r2], i1);
          float2 v0 = upk(a0r[r2]);
          float2 v1 = upk(a1r[r2]);
          *reinterpret_cast<float4*>(dst + r2*128 + 4*pg) = make_float4(v0.x,v0.y,v1.x,v1.y);
        }
      }
      __syncthreads();

      // ---- combine sk-quarter partials ----
      {
        float4* ob = reinterpret_cast<float4*>(qkv + hd*16*128);
        const float4* p1 = reinterpret_cast<const float4*>(aux);
        const float4* p2 = reinterpret_cast<const float4*>(aux + 2048);
        const float4* p3 = reinterpret_cast<const float4*>(aux + 4096);
        float4 o = ob[tid], q1 = p1[tid], q2 = p2[tid], q3 = p3[tid];
        o.x += q1.x + q2.x + q3.x;
        o.y += q1.y + q2.y + q3.y;
        o.z += q1.z + q2.z + q3.z;
        o.w += q1.w + q2.w + q3.w;
        ob[tid] = o;
      }
      __syncthreads();
    }

    // stage out W into aux, out gemm into att
    stage(aux, ow + l*64*64, 4096/4, tid);
    __syncthreads();
    gemm_sm<64,64,false,2>(qkv, aux, obias + l*64, att, tid);
    __syncthreads();
    add_ln(h, att, l1s + l*64, l1b + l*64, aux, tid,
           qkv,        f1w + l*128*64, 8192/4,
           qkv + 8192, f2w + l*64*128, 8192/4);
    __syncthreads();
    gemm_sm<128,64,true,2>(h, qkv, f1b + l*128, att, tid);
    __syncthreads();
    gemm_sm<64,128,false,2>(att, qkv + 8192, f2b + l*64, qkv, tid);
    __syncthreads();
    if (l == 0){
      add_ln(h, qkv, l2s, l2b, aux, tid, att, qw + 12288, 12288/4);
    } else {
      add_ln(h, qkv, l2s + 64, l2b + 64, aux, tid);
    }
    __syncthreads();
  }

  // ---------------- Phase C ----------------
  {
    const int d = tid & 63, oc = tid >> 6;
    float s0 = 0.f;
#pragma unroll
    for (int t = oc*16; t < oc*16 + 16; t++) s0 += h[d*128 + t];
    aux[oc*64 + d] = s0;
  }
  __syncthreads();
  if (tid < 64){
    float hm = 0.f;
#pragma unroll
    for (int o2=0;o2<8;o2++) hm += aux[o2*64 + tid];
    aux[512 + tid] = hm * (1.0f/128.0f);
  }
  __syncthreads();
  if (tid < 32){
    float a = aux[512 + tid], c = aux[512 + 32 + tid];
    float sum = a + c, sq = a*a + c*c;
#pragma unroll
    for (int off=16; off; off>>=1){
      sum += __shfl_xor_sync(0xffffffffu, sum, off);
      sq  += __shfl_xor_sync(0xffffffffu, sq,  off);
    }
    if (tid == 0){
      float m = sum * (1.f/64.f);
      aux[576] = m;
      aux[577] = rsqrtf(sq * (1.f/64.f) - m*m + EPS_);
    }
  }
  __syncthreads();
  if (tid < 64){
    float m = aux[576], inv = aux[577];
    aux[640 + tid] = (aux[512+tid] - m)*inv*__ldg(hls+tid) + __ldg(hlb+tid);
  }
  __syncthreads();
  if (tid < 64){
    float acc = __ldg(h1b + tid);
#pragma unroll 8
    for (int k=0;k<64;k++) acc += aux[640+k]*__ldg(h1w + tid*64 + k);
    aux[704 + tid] = 0.5f*acc*(1.0f + erff(acc*0.70710678118654752f));
  }
  __syncthreads();
  if (tid < 3){
    float acc = __ldg(h2b + tid);
#pragma unroll 8
    for (int k=0;k<64;k++) acc += aux[704+k]*__ldg(h2w + tid*64 + k);
    out[b*3 + tid] = acc;
  }
}

extern "C" void kernel_launch(void* const* d_in, const int* in_sizes, int n_in,
                              void* d_out, int out_size)
{
  const int*   qli    = (const int*)  d_in[0];
  const int*   offs   = (const int*)  d_in[1];
  const float* coords = (const float*)d_in[2];
  const float* vals   = (const float*)d_in[3];
  const float* lg     = (const float*)d_in[4];
  const float* pw     = (const float*)d_in[5];
  const float* pb     = (const float*)d_in[6];
  const float* qw     = (const float*)d_in[7];
  const float* qb     = (const float*)d_in[8];
  const float* ow     = (const float*)d_in[9];
  const float* ob     = (const float*)d_in[10];
  const float* l1s    = (const float*)d_in[11];
  const float* l1b    = (const float*)d_in[12];
  const float* f1w    = (const float*)d_in[13];
  const float* f1b    = (const float*)d_in[14];
  const float* f2w    = (const float*)d_in[15];
  const float* f2b    = (const float*)d_in[16];
  const float* l2s    = (const float*)d_in[17];
  const float* l2b    = (const float*)d_in[18];
  const float* hls    = (const float*)d_in[19];
  const float* hlb    = (const float*)d_in[20];
  const float* h1w    = (const float*)d_in[21];
  const float* h1b    = (const float*)d_in[22];
  const float* h2w    = (const float*)d_in[23];
  const float* h2b    = (const float*)d_in[24];
  float* out = (float*)d_out;
  const int B = in_sizes[0];

  cudaFuncSetAttribute(ff_kernel, cudaFuncAttributeMaxDynamicSharedMemorySize,
                       SMEM_FLOATS * (int)sizeof(float));
  ff_kernel<<<B, 512, SMEM_FLOATS * sizeof(float)>>>(
      qli, offs, coords, vals, lg, pw, pb, qw, qb, ow, ob,
      l1s, l1b, f1w, f1b, f2w, f2b, l2s, l2b,
      hls, hlb, h1w, h1b, h2w, h2b, out);
}

// round 8
// speedup vs baseline: 1.8433x; 1.0382x over previous
#include <cuda_runtime.h>

typedef unsigned long long ULL;

__device__ __forceinline__ ULL pk2(float lo, float hi){
  ULL r; asm("mov.b64 %0, {%1,%2};" : "=l"(r) : "f"(lo), "f"(hi)); return r;
}
__device__ __forceinline__ float2 upk(ULL v){
  float2 r; asm("mov.b64 {%0,%1}, %2;" : "=f"(r.x), "=f"(r.y) : "l"(v)); return r;
}
#define FMA2(d,a,bb,c) asm("fma.rn.f32x2 %0, %1, %2, %3;" : "=l"(d) : "l"(a), "l"(bb), "l"(c))
#define MUL2(d,a,bb)   asm("mul.rn.f32x2 %0, %1, %2;"     : "=l"(d) : "l"(a), "l"(bb))

constexpr int NX_ = 128, NY_ = 128, NT_ = 64;
constexpr float EPS_ = 1e-5f;

constexpr int OFF_H   = 0;         // h[64][128]
constexpr int OFF_QKV = 8192;      // qkv[192][128]; also ff1 W (8192) + ff2 W (8192)
constexpr int OFF_ATT = 32768;     // att[128][128]; also staged qkv W (12288); out W + out C
constexpr int OFF_AUX = 49152;     // AV partials (3*2048) / QK row-psum (2048) / LN scratch
constexpr int OFF_RS  = 55296;     // 128 row inverses (+pad)
constexpr int SMEM_FLOATS = 55808; // 223,232 bytes

__device__ __forceinline__ void stage(float* __restrict__ dst,
                                      const float* __restrict__ src,
                                      int n4, int tid)
{
  const float4* s = reinterpret_cast<const float4*>(src);
  float4* d = reinterpret_cast<float4*>(dst);
  for (int i = tid; i < n4; i += 512) d[i] = s[i];
}

// C[o][s] = act( sum_k A[k][s]*Ws[o*K+k] + Bv[o] ); Ws in SHARED (uniform broadcast reads)
template<int OUT, int K, bool RELU, int TPT>
__device__ __forceinline__ void gemm_sm(const float* __restrict__ A,
                                        const float* __restrict__ Ws,
                                        const float* __restrict__ Bv,
                                        float* __restrict__ C, int tid)
{
  constexpr int NTG = 128/TPT;
  constexpr int NOG = 512/NTG;
  constexpr int TO  = OUT/NOG;
  constexpr int PU  = TPT/2;
  const int tx  = tid & (NTG-1);
  const int g   = tid / NTG;        // warp-uniform
  const int tok = TPT*tx;
  ULL acc[TO][PU];
#pragma unroll
  for (int j=0;j<TO;j++){
    float b = __ldg(Bv + g*TO + j);
    ULL bb = pk2(b,b);
#pragma unroll
    for (int p=0;p<PU;p++) acc[j][p] = bb;
  }
#pragma unroll 2
  for (int k=0;k<K;k+=4){
    ULL a0[PU], a1[PU], a2[PU], a3[PU];
    if (TPT == 4){
      float4 f0 = *reinterpret_cast<const float4*>(A + (k  )*128 + tok);
      float4 f1 = *reinterpret_cast<const float4*>(A + (k+1)*128 + tok);
      float4 f2 = *reinterpret_cast<const float4*>(A + (k+2)*128 + tok);
      float4 f3 = *reinterpret_cast<const float4*>(A + (k+3)*128 + tok);
      a0[0]=pk2(f0.x,f0.y); a0[PU-1]=pk2(f0.z,f0.w);
      a1[0]=pk2(f1.x,f1.y); a1[PU-1]=pk2(f1.z,f1.w);
      a2[0]=pk2(f2.x,f2.y); a2[PU-1]=pk2(f2.z,f2.w);
      a3[0]=pk2(f3.x,f3.y); a3[PU-1]=pk2(f3.z,f3.w);
    } else {
#pragma unroll
      for (int p=0;p<PU;p++){
        a0[p] = *reinterpret_cast<const ULL*>(A + (k  )*128 + tok + 2*p);
        a1[p] = *reinterpret_cast<const ULL*>(A + (k+1)*128 + tok + 2*p);
        a2[p] = *reinterpret_cast<const ULL*>(A + (k+2)*128 + tok + 2*p);
        a3[p] = *reinterpret_cast<const ULL*>(A + (k+3)*128 + tok + 2*p);
      }
    }
#pragma unroll
    for (int j=0;j<TO;j++){
      float4 w = *reinterpret_cast<const float4*>(Ws + (g*TO+j)*K + k);
      ULL w0 = pk2(w.x,w.x), w1 = pk2(w.y,w.y), w2 = pk2(w.z,w.z), w3 = pk2(w.w,w.w);
#pragma unroll
      for (int p=0;p<PU;p++){
        FMA2(acc[j][p], a0[p], w0, acc[j][p]);
        FMA2(acc[j][p], a1[p], w1, acc[j][p]);
        FMA2(acc[j][p], a2[p], w2, acc[j][p]);
        FMA2(acc[j][p], a3[p], w3, acc[j][p]);
      }
    }
  }
#pragma unroll
  for (int j=0;j<TO;j++){
    if (TPT == 4){
      float2 v0 = upk(acc[j][0]);
      float2 v1 = upk(acc[j][PU-1]);
      if (RELU){
        v0.x=fmaxf(v0.x,0.f); v0.y=fmaxf(v0.y,0.f);
        v1.x=fmaxf(v1.x,0.f); v1.y=fmaxf(v1.y,0.f);
      }
      *reinterpret_cast<float4*>(C + (g*TO+j)*128 + tok) = make_float4(v0.x,v0.y,v1.x,v1.y);
    } else {
#pragma unroll
      for (int p=0;p<PU;p++){
        float2 v = upk(acc[j][p]);
        if (RELU){ v.x = fmaxf(v.x,0.f); v.y = fmaxf(v.y,0.f); }
        *reinterpret_cast<float2*>(C + (g*TO+j)*128 + tok + 2*p) = v;
      }
    }
  }
}

// h = LN(h + r), with up to two staging jobs overlapped into pass 1
__device__ __forceinline__ void add_ln(float* __restrict__ h,
                                       const float* __restrict__ r,
                                       const float* __restrict__ gs,
                                       const float* __restrict__ gb,
                                       float* __restrict__ aux, int tid,
                                       float* wdst0 = nullptr, const float* wsrc0 = nullptr, int n40 = 0,
                                       float* wdst1 = nullptr, const float* wsrc1 = nullptr, int n41 = 0)
{
  const int s = tid & 127, g = tid >> 7;
  float sum=0.f, sq=0.f;
#pragma unroll
  for (int d=16*g; d<16*g+16; d++){
    float x = h[d*128+s] + r[d*128+s];
    h[d*128+s] = x;
    sum += x; sq += x*x;
  }
  aux[g*128+s] = sum;
  aux[512 + g*128+s] = sq;
  if (wsrc0) stage(wdst0, wsrc0, n40, tid);
  if (wsrc1) stage(wdst1, wsrc1, n41, tid);
  __syncthreads();
  if (tid < 128){
    float S = aux[tid] + aux[128+tid] + aux[256+tid] + aux[384+tid];
    float Q = aux[512+tid] + aux[640+tid] + aux[768+tid] + aux[896+tid];
    float m = S * (1.f/64.f);
    float inv = rsqrtf(Q * (1.f/64.f) - m*m + EPS_);
    aux[1024+tid] = m;
    aux[1152+tid] = inv;
  }
  __syncthreads();
  {
    float m = aux[1024+s], inv = aux[1152+s];
#pragma unroll
    for (int d=16*g; d<16*g+16; d++){
      h[d*128+s] = (h[d*128+s] - m)*inv*__ldg(gs+d) + __ldg(gb+d);
    }
  }
}

__device__ __forceinline__ float dper(float diff, float L){
  float m = fmodf(diff + 0.5f*L, L);
  if (m < 0.f) m += L;
  return m - 0.5f*L;
}

__global__ void __launch_bounds__(512, 1)
ff_kernel(const int* __restrict__ q_lin_idx, const int* __restrict__ offs,
          const float* __restrict__ coords, const float* __restrict__ vals,
          const float* __restrict__ lg,
          const float* __restrict__ pw, const float* __restrict__ pb,
          const float* __restrict__ qw, const float* __restrict__ qbias,
          const float* __restrict__ ow, const float* __restrict__ obias,
          const float* __restrict__ l1s, const float* __restrict__ l1b,
          const float* __restrict__ f1w, const float* __restrict__ f1b,
          const float* __restrict__ f2w, const float* __restrict__ f2b,
          const float* __restrict__ l2s, const float* __restrict__ l2b,
          const float* __restrict__ hls, const float* __restrict__ hlb,
          const float* __restrict__ h1w, const float* __restrict__ h1b,
          const float* __restrict__ h2w, const float* __restrict__ h2b,
          float* __restrict__ out)
{
  extern __shared__ float sm[];
  float* h    = sm + OFF_H;
  float* qkv  = sm + OFF_QKV;
  float* att  = sm + OFF_ATT;
  float* aux  = sm + OFF_AUX;
  float* rs   = sm + OFF_RS;   // 128 inverses

  const int tid = threadIdx.x;
  const int b   = blockIdx.x;

  // ---------------- Phase A: gather + input projection (+ stage layer-0 qkv W) ----------------
  {
    const int s = tid & 127, g = tid >> 7;
    int qi = __ldg(q_lin_idx + b);
    int i  = qi >> 13;
    int rr = qi & 8191;
    int j  = rr >> 6;
    int kk = rr & 63;
    int di = __ldg(offs + 3*s), dj = __ldg(offs + 3*s + 1), dk = __ldg(offs + 3*s + 2);
    int I = (i + di) & (NX_-1);
    int J = (j + dj) & (NY_-1);
    int T = min(max(kk + dk, 0), NT_-1);
    int nb = (I << 13) + (J << 6) + T;
    float qx = __ldg(coords + 3*qi), qy = __ldg(coords + 3*qi + 1), qt = __ldg(coords + 3*qi + 2);
    float nx = __ldg(coords + 3*nb), ny = __ldg(coords + 3*nb + 1), nt = __ldg(coords + 3*nb + 2);
    float g0 = expf(__ldg(lg+0)), g1 = expf(__ldg(lg+1)), g2 = expf(__ldg(lg+2));
    float f0 = dper(nx - qx, 2.0f) * g0;
    float f1 = dper(ny - qy, 2.0f) * g1;
    float f2 = (nt - qt) * g2;
    float f3 = __ldg(vals + 3*nb), f4 = __ldg(vals + 3*nb + 1), f5 = __ldg(vals + 3*nb + 2);
#pragma unroll
    for (int d = g*16; d < g*16 + 16; d++){
      float a = __ldg(pb + d);
      a += __ldg(pw + 6*d + 0)*f0 + __ldg(pw + 6*d + 1)*f1 + __ldg(pw + 6*d + 2)*f2
         + __ldg(pw + 6*d + 3)*f3 + __ldg(pw + 6*d + 4)*f4 + __ldg(pw + 6*d + 5)*f5;
      h[d*128 + s] = a;
    }
    stage(att, qw, 12288/4, tid);
  }
  __syncthreads();

  // ---------------- Phase B: 2 transformer layers ----------------
  for (int l = 0; l < 2; l++){
    gemm_sm<192,64,false,4>(h, att, qbias + l*192, qkv, tid);
    __syncthreads();

    for (int hd = 0; hd < 4; hd++){
      // ---- QK^T + fused exp + fused row partial-sum ----
      {
        const float* qb2 = qkv + (hd*16)*128;
        const float* kb  = qkv + (64 + hd*16)*128;
        const int tx = tid & 31;   // sq tile of 4 (lane-contiguous)
        const int ty = tid >> 5;   // sk tile of 8 (warp-uniform)
        ULL acc[8][2];
        ULL z = pk2(0.f, 0.f);
#pragma unroll
        for (int jj=0;jj<8;jj++){ acc[jj][0]=z; acc[jj][1]=z; }
#pragma unroll 4
        for (int di=0; di<16; di++){
          float4 qf = *reinterpret_cast<const float4*>(qb2 + di*128 + 4*tx);
          ULL q0 = pk2(qf.x,qf.y), q1 = pk2(qf.z,qf.w);
          float4 k0 = *reinterpret_cast<const float4*>(kb + di*128 + 8*ty);
          float4 k1 = *reinterpret_cast<const float4*>(kb + di*128 + 8*ty + 4);
          float kvv[8] = {k0.x,k0.y,k0.z,k0.w,k1.x,k1.y,k1.z,k1.w};
#pragma unroll
          for (int jj=0;jj<8;jj++){
            ULL kd = pk2(kvv[jj], kvv[jj]);
            FMA2(acc[jj][0], q0, kd, acc[jj][0]);
            FMA2(acc[jj][1], q1, kd, acc[jj][1]);
          }
        }
        float4 psum = make_float4(0.f,0.f,0.f,0.f);
#pragma unroll
        for (int jj=0;jj<8;jj++){
          float2 v0 = upk(acc[jj][0]);
          float2 v1 = upk(acc[jj][1]);
          float4 e;
          e.x = __expf(0.25f * v0.x);
          e.y = __expf(0.25f * v0.y);
          e.z = __expf(0.25f * v1.x);
          e.w = __expf(0.25f * v1.y);
          *reinterpret_cast<float4*>(att + (8*ty+jj)*128 + 4*tx) = e;
          psum.x += e.x; psum.y += e.y; psum.z += e.z; psum.w += e.w;
        }
        *reinterpret_cast<float4*>(aux + ty*128 + 4*tx) = psum;  // 16 partial rows
      }
      __syncthreads();

      // ---- fold 16 row partials -> 1/rowsum ----
      if (tid < 128){
        float s0 = 0.f;
#pragma unroll
        for (int r2=0;r2<16;r2++) s0 += aux[r2*128 + tid];
        rs[tid] = 1.0f / s0;
      }
      __syncthreads();

      // ---- AV: o[dv][sq] = inv[sq] * sum_sk att[sk][sq]*v[dv][sk]
      //      pg: 64 sq-pairs, dq: 2 dv-octets, hf: 4 sk-quarters ----
      {
        const int pg = tid & 63;        // sq pair: sq = 2*pg
        const int dq = (tid>>6) & 1;    // dv octet
        const int hf = tid >> 7;        // sk quarter
        const float* vb = qkv + (128 + hd*16 + 8*dq)*128;
        ULL acc[8];
        ULL z = pk2(0.f,0.f);
#pragma unroll
        for (int r2=0;r2<8;r2++) acc[r2]=z;
        for (int sk0 = hf*32; sk0 < hf*32 + 32; sk0 += 4){
          float4 vr[8];
#pragma unroll
          for (int r2=0;r2<8;r2++)
            vr[r2] = *reinterpret_cast<const float4*>(vb + r2*128 + sk0);
          ULL a0 = *reinterpret_cast<const ULL*>(att + (sk0  )*128 + 2*pg);
          ULL a1 = *reinterpret_cast<const ULL*>(att + (sk0+1)*128 + 2*pg);
          ULL a2 = *reinterpret_cast<const ULL*>(att + (sk0+2)*128 + 2*pg);
          ULL a3 = *reinterpret_cast<const ULL*>(att + (sk0+3)*128 + 2*pg);
#pragma unroll
          for (int r2=0;r2<8;r2++){
            FMA2(acc[r2], a0, pk2(vr[r2].x, vr[r2].x), acc[r2]);
            FMA2(acc[r2], a1, pk2(vr[r2].y, vr[r2].y), acc[r2]);
            FMA2(acc[r2], a2, pk2(vr[r2].z, vr[r2].z), acc[r2]);
            FMA2(acc[r2], a3, pk2(vr[r2].w, vr[r2].w), acc[r2]);
          }
        }
        ULL iv = *reinterpret_cast<const ULL*>(rs + 2*pg);
        float* dst = (hf==0) ? (qkv + (hd*16 + 8*dq)*128)
                             : (aux + (hf-1)*2048 + 8*dq*128);
#pragma unroll
        for (int r2=0;r2<8;r2++){
          MUL2(acc[r2], acc[r2], iv);
          *reinterpret_cast<ULL*>(dst + r2*128 + 2*pg) = acc[r2];
        }
      }
      __syncthreads();

      // ---- combine sk-quarter partials (+ stage out W on last head) ----
      {
        float4* ob = reinterpret_cast<float4*>(qkv + hd*16*128);
        const float4* p1 = reinterpret_cast<const float4*>(aux);
        const float4* p2 = reinterpret_cast<const float4*>(aux + 2048);
        const float4* p3 = reinterpret_cast<const float4*>(aux + 4096);
        float4 o = ob[tid], q1 = p1[tid], q2 = p2[tid], q3 = p3[tid];
        o.x += q1.x + q2.x + q3.x;
        o.y += q1.y + q2.y + q3.y;
        o.z += q1.z + q2.z + q3.z;
        o.w += q1.w + q2.w + q3.w;
        ob[tid] = o;
        if (hd == 3) stage(att, ow + l*64*64, 4096/4, tid);
      }
      __syncthreads();
    }

    // out gemm: W staged in att[0:4096), C -> att[4096:12288)
    gemm_sm<64,64,false,2>(qkv, att, obias + l*64, att + 4096, tid);
    __syncthreads();
    add_ln(h, att + 4096, l1s + l*64, l1b + l*64, aux, tid,
           qkv,        f1w + l*128*64, 8192/4,
           qkv + 8192, f2w + l*64*128, 8192/4);
    __syncthreads();
    gemm_sm<128,64,true,2>(h, qkv, f1b + l*128, att, tid);
    __syncthreads();
    gemm_sm<64,128,false,2>(att, qkv + 8192, f2b + l*64, qkv, tid);
    __syncthreads();
    if (l == 0){
      add_ln(h, qkv, l2s, l2b, aux, tid, att, qw + 12288, 12288/4);
    } else {
      add_ln(h, qkv, l2s + 64, l2b + 64, aux, tid);
    }
    __syncthreads();
  }

  // ---------------- Phase C ----------------
  {
    const int d = tid & 63, oc = tid >> 6;
    float s0 = 0.f;
#pragma unroll
    for (int t = oc*16; t < oc*16 + 16; t++) s0 += h[d*128 + t];
    aux[oc*64 + d] = s0;
  }
  __syncthreads();
  if (tid < 64){
    float hm = 0.f;
#pragma unroll
    for (int o2=0;o2<8;o2++) hm += aux[o2*64 + tid];
    aux[512 + tid] = hm * (1.0f/128.0f);
  }
  __syncthreads();
  if (tid < 32){
    float a = aux[512 + tid], c = aux[512 + 32 + tid];
    float sum = a + c, sq = a*a + c*c;
#pragma unroll
    for (int off=16; off; off>>=1){
      sum += __shfl_xor_sync(0xffffffffu, sum, off);
      sq  += __shfl_xor_sync(0xffffffffu, sq,  off);
    }
    if (tid == 0){
      float m = sum * (1.f/64.f);
      aux[576] = m;
      aux[577] = rsqrtf(sq * (1.f/64.f) - m*m + EPS_);
    }
  }
  __syncthreads();
  if (tid < 64){
    float m = aux[576], inv = aux[577];
    aux[640 + tid] = (aux[512+tid] - m)*inv*__ldg(hls+tid) + __ldg(hlb+tid);
  }
  __syncthreads();
  if (tid < 64){
    float acc = __ldg(h1b + tid);
#pragma unroll 8
    for (int k=0;k<64;k++) acc += aux[640+k]*__ldg(h1w + tid*64 + k);
    aux[704 + tid] = 0.5f*acc*(1.0f + erff(acc*0.70710678118654752f));
  }
  __syncthreads();
  if (tid < 3){
    float acc = __ldg(h2b + tid);
#pragma unroll 8
    for (int k=0;k<64;k++) acc += aux[704+k]*__ldg(h2w + tid*64 + k);
    out[b*3 + tid] = acc;
  }
}

extern "C" void kernel_launch(void* const* d_in, const int* in_sizes, int n_in,
                              void* d_out, int out_size)
{
  const int*   qli    = (const int*)  d_in[0];
  const int*   offs   = (const int*)  d_in[1];
  const float* coords = (const float*)d_in[2];
  const float* vals   = (const float*)d_in[3];
  const float* lg     = (const float*)d_in[4];
  const float* pw     = (const float*)d_in[5];
  const float* pb     = (const float*)d_in[6];
  const float* qw     = (const float*)d_in[7];
  const float* qb     = (const float*)d_in[8];
  const float* ow     = (const float*)d_in[9];
  const float* ob     = (const float*)d_in[10];
  const float* l1s    = (const float*)d_in[11];
  const float* l1b    = (const float*)d_in[12];
  const float* f1w    = (const float*)d_in[13];
  const float* f1b    = (const float*)d_in[14];
  const float* f2w    = (const float*)d_in[15];
  const float* f2b    = (const float*)d_in[16];
  const float* l2s    = (const float*)d_in[17];
  const float* l2b    = (const float*)d_in[18];
  const float* hls    = (const float*)d_in[19];
  const float* hlb    = (const float*)d_in[20];
  const float* h1w    = (const float*)d_in[21];
  const float* h1b    = (const float*)d_in[22];
  const float* h2w    = (const float*)d_in[23];
  const float* h2b    = (const float*)d_in[24];
  float* out = (float*)d_out;
  const int B = in_sizes[0];

  cudaFuncSetAttribute(ff_kernel, cudaFuncAttributeMaxDynamicSharedMemorySize,
                       SMEM_FLOATS * (int)sizeof(float));
  ff_kernel<<<B, 512, SMEM_FLOATS * sizeof(float)>>>(
      qli, offs, coords, vals, lg, pw, pb, qw, qb, ow, ob,
      l1s, l1b, f1w, f1b, f2w, f2b, l2s, l2b,
      hls, hlb, h1w, h1b, h2w, h2b, out);
}